// round 1
// baseline (speedup 1.0000x reference)
#include <cuda_runtime.h>
#include <math.h>

// Problem constants
#define NSEQ 256
#define LRES 384
#define DM   256
#define DP   128
#define NH   8
#define DHD  32
#define HD   256           // NH*DHD
#define NLROWS (NSEQ*LRES) // 98304
#define EPS 1e-5f

// -------- scratch (device globals; no allocation allowed) --------
__device__ float g_m[NLROWS * DM];        // LN(msa)
__device__ float g_qsw[LRES * HD];        // q_sw (scaled)
__device__ float g_ksw[NLROWS * HD];      // k_sw
__device__ float g_q[NLROWS * HD];        // m@Wq (unweighted)
__device__ float g_k[NLROWS * HD];        // m@Wk * 1/sqrt(DH)
__device__ float g_v[NLROWS * HD];        // m@Wv
__device__ float g_gate[NLROWS * HD];     // sigmoid(m@Wg + bg)
__device__ float g_ao[NLROWS * HD];       // attention output (pre-gate)
__device__ float g_sw[NLROWS * NH];       // seq_weight [(n*L+i)*H + h]
__device__ float g_logits[NH * LRES * LRES]; // [h][i][j]
__device__ float g_bias[NH * LRES * LRES];   // [h][i][j]
__device__ float g_attn[NH * LRES * LRES];   // [h][i][j]

// =========================================================================
// K1: LayerNorm over msa rows (D=256). One block (256 thr) per row.
// =========================================================================
__global__ void __launch_bounds__(256) ln_msa_kernel(
    const float* __restrict__ x, const float* __restrict__ g,
    const float* __restrict__ b, float* __restrict__ out)
{
    const size_t row = blockIdx.x;
    const int t = threadIdx.x;
    float v = x[row * DM + t];
    float s = v, s2 = v * v;
    #pragma unroll
    for (int o = 16; o; o >>= 1) {
        s  += __shfl_xor_sync(0xffffffffu, s,  o);
        s2 += __shfl_xor_sync(0xffffffffu, s2, o);
    }
    __shared__ float ss[8], ss2[8], fin[2];
    const int w = t >> 5, lane = t & 31;
    if (!lane) { ss[w] = s; ss2[w] = s2; }
    __syncthreads();
    if (w == 0) {
        float a  = (lane < 8) ? ss[lane]  : 0.f;
        float a2 = (lane < 8) ? ss2[lane] : 0.f;
        #pragma unroll
        for (int o = 4; o; o >>= 1) {
            a  += __shfl_xor_sync(0xffffffffu, a,  o);
            a2 += __shfl_xor_sync(0xffffffffu, a2, o);
        }
        if (!lane) {
            float mu  = a * (1.f / DM);
            float var = a2 * (1.f / DM) - mu * mu;
            fin[0] = mu; fin[1] = rsqrtf(var + EPS);
        }
    }
    __syncthreads();
    out[row * DM + t] = (v - fin[0]) * fin[1] * g[t] + b[t];
}

// =========================================================================
// K2/K8: generic SGEMM  C[M,N] = A[M,K] (optionally * emul elementwise) @ B[K,N]
//        epilogue: (+bias[col]) * outScale, optional sigmoid.
// BM=BN=64, BK=16, 256 threads, 4x4 per thread, float4 everywhere.
// M % 64 == 0, N % 64 == 0, K % 16 == 0 for all call sites.
// =========================================================================
__global__ void __launch_bounds__(256) sgemm_kernel(
    const float* __restrict__ A, const float* __restrict__ B, float* __restrict__ C,
    const float* __restrict__ bias, const float* __restrict__ emul,
    int M, int K, int N, float outScale, int sigm)
{
    __shared__ __align__(16) float As[16][68];  // [k][m] (padded)
    __shared__ __align__(16) float Bs[16][64];  // [k][n]
    const int tid = threadIdx.x;
    const int m0 = blockIdx.x * 64;
    const int n0 = blockIdx.y * 64;
    const int rA = tid >> 2, cA = tid & 3;   // A load: row, float4-col
    const int rB = tid >> 4, cB = tid & 15;  // B load: k-row, float4-col
    const int ty = tid >> 4, tx = tid & 15;
    float acc[4][4] = {};
    const float* Aptr = A + (size_t)(m0 + rA) * K + 4 * cA;
    const float* Eptr = emul ? emul + (size_t)(m0 + rA) * K + 4 * cA : nullptr;
    const float* Bptr = B + (size_t)rB * N + n0 + 4 * cB;

    for (int k0 = 0; k0 < K; k0 += 16) {
        float4 a4 = *(const float4*)(Aptr + k0);
        if (Eptr) {
            float4 e4 = *(const float4*)(Eptr + k0);
            a4.x *= e4.x; a4.y *= e4.y; a4.z *= e4.z; a4.w *= e4.w;
        }
        As[4*cA+0][rA] = a4.x; As[4*cA+1][rA] = a4.y;
        As[4*cA+2][rA] = a4.z; As[4*cA+3][rA] = a4.w;
        *(float4*)&Bs[rB][4*cB] = *(const float4*)(Bptr + (size_t)k0 * N);
        __syncthreads();
        #pragma unroll
        for (int kk = 0; kk < 16; kk++) {
            float4 av = *(const float4*)&As[kk][ty * 4];
            float4 bv = *(const float4*)&Bs[kk][tx * 4];
            float ar[4] = {av.x, av.y, av.z, av.w};
            float br[4] = {bv.x, bv.y, bv.z, bv.w};
            #pragma unroll
            for (int i = 0; i < 4; i++)
                #pragma unroll
                for (int j = 0; j < 4; j++)
                    acc[i][j] = fmaf(ar[i], br[j], acc[i][j]);
        }
        __syncthreads();
    }
    #pragma unroll
    for (int i = 0; i < 4; i++) {
        const int row = m0 + ty * 4 + i;
        float o[4];
        #pragma unroll
        for (int j = 0; j < 4; j++) {
            float vv = acc[i][j];
            const int col = n0 + tx * 4 + j;
            if (bias) vv += bias[col];
            vv *= outScale;
            if (sigm) vv = 1.0f / (1.0f + expf(-vv));
            o[j] = vv;
        }
        *(float4*)(C + (size_t)row * N + n0 + tx * 4) =
            make_float4(o[0], o[1], o[2], o[3]);
    }
}

// =========================================================================
// K3: seq-weight: sw_logits[n,i,h] = dot_d(q_sw[i,h,:], k_sw[n,i,h,:]),
//     softmax over n (=thread index, 256 threads). grid (L, H).
// =========================================================================
__global__ void __launch_bounds__(256) seqw_kernel(
    const float* __restrict__ qsw, const float* __restrict__ ksw,
    float* __restrict__ sw)
{
    const int i = blockIdx.x, h = blockIdx.y;
    const int t = threadIdx.x;            // = n
    __shared__ __align__(16) float qs[DHD];
    __shared__ float red[8];
    if (t < DHD) qs[t] = qsw[(size_t)i * HD + h * DHD + t];
    __syncthreads();
    const float* kp = ksw + ((size_t)t * LRES + i) * HD + h * DHD;
    float dot = 0.f;
    #pragma unroll
    for (int c = 0; c < 8; c++) {
        float4 k4 = *(const float4*)(kp + 4 * c);
        float4 q4 = *(const float4*)(qs + 4 * c);
        dot += k4.x * q4.x + k4.y * q4.y + k4.z * q4.z + k4.w * q4.w;
    }
    const int w = t >> 5, lane = t & 31;
    float mx = dot;
    #pragma unroll
    for (int o = 16; o; o >>= 1) mx = fmaxf(mx, __shfl_xor_sync(0xffffffffu, mx, o));
    if (!lane) red[w] = mx;
    __syncthreads();
    mx = red[0];
    #pragma unroll
    for (int x = 1; x < 8; x++) mx = fmaxf(mx, red[x]);
    const float e = expf(dot - mx);
    float s = e;
    #pragma unroll
    for (int o = 16; o; o >>= 1) s += __shfl_xor_sync(0xffffffffu, s, o);
    __syncthreads();
    if (!lane) red[w] = s;
    __syncthreads();
    float S = 0.f;
    #pragma unroll
    for (int x = 0; x < 8; x++) S += red[x];
    sw[((size_t)t * LRES + i) * NH + h] = e / S;
}

// =========================================================================
// K4: logits[h][i][j] = sum_{n,d} (q[n,i,h,d]*sw[n,i,h]) * k[n,j,h,d]
//     GEMM per head: M=N=384 (i,j), K=8192 (n x d). grid (6,6,8).
// =========================================================================
__global__ void __launch_bounds__(256) logits_kernel(
    const float* __restrict__ q, const float* __restrict__ k,
    const float* __restrict__ sw, float* __restrict__ out)
{
    __shared__ __align__(16) float As[32][68];  // [d][i]
    __shared__ __align__(16) float Bs[32][68];  // [d][j]
    const int tid = threadIdx.x;
    const int i0 = blockIdx.x * 64;
    const int j0 = blockIdx.y * 64;
    const int h  = blockIdx.z;
    const int ty = tid >> 4, tx = tid & 15;
    float acc[4][4] = {};
    for (int n = 0; n < NSEQ; n++) {
        const size_t rowi = (size_t)n * LRES + i0;
        const size_t rowj = (size_t)n * LRES + j0;
        #pragma unroll
        for (int s = 0; s < 2; s++) {
            const int idx = tid + 256 * s;
            const int r = idx >> 3;     // 0..63
            const int c = idx & 7;      // float4 within 32 d
            float4 a4 = *(const float4*)(q + (rowi + r) * HD + h * DHD + 4 * c);
            const float swv = sw[(rowi + r) * NH + h];
            a4.x *= swv; a4.y *= swv; a4.z *= swv; a4.w *= swv;
            As[4*c+0][r] = a4.x; As[4*c+1][r] = a4.y;
            As[4*c+2][r] = a4.z; As[4*c+3][r] = a4.w;
            float4 b4 = *(const float4*)(k + (rowj + r) * HD + h * DHD + 4 * c);
            Bs[4*c+0][r] = b4.x; Bs[4*c+1][r] = b4.y;
            Bs[4*c+2][r] = b4.z; Bs[4*c+3][r] = b4.w;
        }
        __syncthreads();
        #pragma unroll
        for (int kk = 0; kk < 32; kk++) {
            float4 av = *(const float4*)&As[kk][ty * 4];
            float4 bv = *(const float4*)&Bs[kk][tx * 4];
            float ar[4] = {av.x, av.y, av.z, av.w};
            float br[4] = {bv.x, bv.y, bv.z, bv.w};
            #pragma unroll
            for (int i = 0; i < 4; i++)
                #pragma unroll
                for (int j = 0; j < 4; j++)
                    acc[i][j] = fmaf(ar[i], br[j], acc[i][j]);
        }
        __syncthreads();
    }
    const size_t ob = (size_t)h * LRES * LRES;
    #pragma unroll
    for (int i = 0; i < 4; i++) {
        *(float4*)(out + ob + (size_t)(i0 + ty * 4 + i) * LRES + j0 + tx * 4) =
            make_float4(acc[i][0], acc[i][1], acc[i][2], acc[i][3]);
    }
}

// =========================================================================
// K5: pair bias: bias[h][i][j] = LN(pair[i,j,:]) @ Wb[:,h]. One warp per (i,j).
// =========================================================================
__global__ void __launch_bounds__(256) pairbias_kernel(
    const float* __restrict__ pair, const float* __restrict__ g,
    const float* __restrict__ b, const float* __restrict__ Wb,
    float* __restrict__ bias)
{
    const int w = threadIdx.x >> 5, lane = threadIdx.x & 31;
    const size_t p = (size_t)blockIdx.x * 8 + w;      // i*LRES + j
    float4 v = *(const float4*)(pair + p * DP + lane * 4);
    float s  = v.x + v.y + v.z + v.w;
    float s2 = v.x * v.x + v.y * v.y + v.z * v.z + v.w * v.w;
    #pragma unroll
    for (int o = 16; o; o >>= 1) {
        s  += __shfl_xor_sync(0xffffffffu, s,  o);
        s2 += __shfl_xor_sync(0xffffffffu, s2, o);
    }
    const float mu   = s * (1.f / DP);
    const float rstd = rsqrtf(s2 * (1.f / DP) - mu * mu + EPS);
    float xv[4] = {v.x, v.y, v.z, v.w};
    float acc[8] = {};
    #pragma unroll
    for (int c = 0; c < 4; c++) {
        const int d = lane * 4 + c;
        const float y = (xv[c] - mu) * rstd * g[d] + b[d];
        const float* wr = Wb + d * NH;
        #pragma unroll
        for (int hh = 0; hh < 8; hh++) acc[hh] = fmaf(y, wr[hh], acc[hh]);
    }
    #pragma unroll
    for (int hh = 0; hh < 8; hh++) {
        float a = acc[hh];
        #pragma unroll
        for (int o = 16; o; o >>= 1) a += __shfl_xor_sync(0xffffffffu, a, o);
        if (lane == hh) bias[(size_t)hh * LRES * LRES + p] = a;
    }
}

// =========================================================================
// K6: attn[h][i][:] = softmax_j(logits + bias). grid (L, H), 128 thr, 3 j each.
// =========================================================================
__global__ void __launch_bounds__(128) rowsoftmax_kernel(
    const float* __restrict__ logits, const float* __restrict__ bias,
    float* __restrict__ attn)
{
    const int i = blockIdx.x, h = blockIdx.y;
    const size_t base = ((size_t)h * LRES + i) * LRES;
    const int t = threadIdx.x;
    __shared__ float red[4];
    float x[3];
    #pragma unroll
    for (int r = 0; r < 3; r++) {
        const int j = t + r * 128;
        x[r] = logits[base + j] + bias[base + j];
    }
    float mx = fmaxf(fmaxf(x[0], x[1]), x[2]);
    #pragma unroll
    for (int o = 16; o; o >>= 1) mx = fmaxf(mx, __shfl_xor_sync(0xffffffffu, mx, o));
    const int w = t >> 5, lane = t & 31;
    if (!lane) red[w] = mx;
    __syncthreads();
    mx = fmaxf(fmaxf(red[0], red[1]), fmaxf(red[2], red[3]));
    float e[3], sum = 0.f;
    #pragma unroll
    for (int r = 0; r < 3; r++) { e[r] = expf(x[r] - mx); sum += e[r]; }
    #pragma unroll
    for (int o = 16; o; o >>= 1) sum += __shfl_xor_sync(0xffffffffu, sum, o);
    __syncthreads();
    if (!lane) red[w] = sum;
    __syncthreads();
    const float inv = 1.f / (red[0] + red[1] + red[2] + red[3]);
    #pragma unroll
    for (int r = 0; r < 3; r++) attn[base + t + r * 128] = e[r] * inv;
}

// =========================================================================
// K7: ao[n,i,h,d] = sum_j attn[h][i][j] * v[n,j,h,d]
//     GEMM per head: M=384 (i), N'=8192 (n,d), K=384 (j). grid (6,128,8).
// =========================================================================
__global__ void __launch_bounds__(256) attnout_kernel(
    const float* __restrict__ attn, const float* __restrict__ v,
    float* __restrict__ ao)
{
    __shared__ __align__(16) float As[16][68];  // [j][i]
    __shared__ __align__(16) float Bs[16][64];  // [j][nd]
    const int tid = threadIdx.x;
    const int i0 = blockIdx.x * 64;
    const int h  = blockIdx.z;
    const int ty = tid >> 4, tx = tid & 15;
    const int rA = tid >> 2, cA = tid & 3;
    const int rB = tid >> 4, cB = tid & 15;
    const int nB = (blockIdx.y << 1) + (cB >> 3);
    const int dB = (cB & 7) * 4;
    const float* Ah = attn + (size_t)h * LRES * LRES;
    float acc[4][4] = {};
    for (int j0 = 0; j0 < LRES; j0 += 16) {
        float4 a4 = *(const float4*)(Ah + (size_t)(i0 + rA) * LRES + j0 + 4 * cA);
        As[4*cA+0][rA] = a4.x; As[4*cA+1][rA] = a4.y;
        As[4*cA+2][rA] = a4.z; As[4*cA+3][rA] = a4.w;
        *(float4*)&Bs[rB][4*cB] =
            *(const float4*)(v + ((size_t)nB * LRES + j0 + rB) * HD + h * DHD + dB);
        __syncthreads();
        #pragma unroll
        for (int kk = 0; kk < 16; kk++) {
            float4 av = *(const float4*)&As[kk][ty * 4];
            float4 bv = *(const float4*)&Bs[kk][tx * 4];
            float ar[4] = {av.x, av.y, av.z, av.w};
            float br[4] = {bv.x, bv.y, bv.z, bv.w};
            #pragma unroll
            for (int i = 0; i < 4; i++)
                #pragma unroll
                for (int j = 0; j < 4; j++)
                    acc[i][j] = fmaf(ar[i], br[j], acc[i][j]);
        }
        __syncthreads();
    }
    const int nOut = (blockIdx.y << 1) + (tx >> 3);
    const int dOut = (tx & 7) * 4;
    #pragma unroll
    for (int i = 0; i < 4; i++) {
        *(float4*)(ao + ((size_t)nOut * LRES + i0 + ty * 4 + i) * HD + h * DHD + dOut) =
            make_float4(acc[i][0], acc[i][1], acc[i][2], acc[i][3]);
    }
}

// =========================================================================
// launcher
// =========================================================================
extern "C" void kernel_launch(void* const* d_in, const int* in_sizes, int n_in,
                              void* d_out, int out_size)
{
    const float* msa       = (const float*)d_in[0];
    const float* pair      = (const float*)d_in[1];
    const float* ln_msa_g  = (const float*)d_in[2];
    const float* ln_msa_b  = (const float*)d_in[3];
    const float* ln_pair_g = (const float*)d_in[4];
    const float* ln_pair_b = (const float*)d_in[5];
    const float* Wq_sw     = (const float*)d_in[6];
    const float* bq_sw     = (const float*)d_in[7];
    const float* Wk_sw     = (const float*)d_in[8];
    const float* bk_sw     = (const float*)d_in[9];
    const float* Wq        = (const float*)d_in[10];
    const float* Wk        = (const float*)d_in[11];
    const float* Wv        = (const float*)d_in[12];
    const float* Wb        = (const float*)d_in[13];
    const float* Wg        = (const float*)d_in[14];
    const float* bg        = (const float*)d_in[15];
    const float* Wo        = (const float*)d_in[16];
    const float* bo        = (const float*)d_in[17];
    float* out = (float*)d_out;

    float *m_, *qsw_, *ksw_, *q_, *k_, *v_, *gate_, *ao_, *sw_, *logits_, *bias_, *attn_;
    cudaGetSymbolAddress((void**)&m_,      g_m);
    cudaGetSymbolAddress((void**)&qsw_,    g_qsw);
    cudaGetSymbolAddress((void**)&ksw_,    g_ksw);
    cudaGetSymbolAddress((void**)&q_,      g_q);
    cudaGetSymbolAddress((void**)&k_,      g_k);
    cudaGetSymbolAddress((void**)&v_,      g_v);
    cudaGetSymbolAddress((void**)&gate_,   g_gate);
    cudaGetSymbolAddress((void**)&ao_,     g_ao);
    cudaGetSymbolAddress((void**)&sw_,     g_sw);
    cudaGetSymbolAddress((void**)&logits_, g_logits);
    cudaGetSymbolAddress((void**)&bias_,   g_bias);
    cudaGetSymbolAddress((void**)&attn_,   g_attn);

    const float scale = 0.17677669529663687f;  // 1/sqrt(32)

    // K1: LN(msa)
    ln_msa_kernel<<<NLROWS, 256>>>(msa, ln_msa_g, ln_msa_b, m_);

    // K2: projections
    dim3 gBig(NLROWS / 64, DM / 64);
    sgemm_kernel<<<gBig, 256>>>(m_, Wk_sw, ksw_, bk_sw, nullptr, NLROWS, DM, HD, 1.f, 0);
    sgemm_kernel<<<dim3(LRES / 64, DM / 64), 256>>>(m_, Wq_sw, qsw_, bq_sw, nullptr, LRES, DM, HD, scale, 0);
    sgemm_kernel<<<gBig, 256>>>(m_, Wq, q_, nullptr, nullptr, NLROWS, DM, HD, 1.f, 0);
    sgemm_kernel<<<gBig, 256>>>(m_, Wk, k_, nullptr, nullptr, NLROWS, DM, HD, scale, 0);
    sgemm_kernel<<<gBig, 256>>>(m_, Wv, v_, nullptr, nullptr, NLROWS, DM, HD, 1.f, 0);
    sgemm_kernel<<<gBig, 256>>>(m_, Wg, gate_, bg, nullptr, NLROWS, DM, HD, 1.f, 1);

    // K3: sequence weights (softmax over n)
    seqw_kernel<<<dim3(LRES, NH), 256>>>(qsw_, ksw_, sw_);

    // K4: logits (contract n,d)
    logits_kernel<<<dim3(LRES / 64, LRES / 64, NH), 256>>>(q_, k_, sw_, logits_);

    // K5: pair bias
    pairbias_kernel<<<(LRES * LRES) / 8, 256>>>(pair, ln_pair_g, ln_pair_b, Wb, bias_);

    // K6: softmax over j
    rowsoftmax_kernel<<<dim3(LRES, NH), 128>>>(logits_, bias_, attn_);

    // K7: attn @ v
    attnout_kernel<<<dim3(LRES / 64, (NSEQ * DHD) / 64, NH), 256>>>(attn_, v_, ao_);

    // K8: (ao * gate) @ Wo + bo
    sgemm_kernel<<<gBig, 256>>>(ao_, Wo, out, bo, gate_, NLROWS, HD, DM, 1.f, 0);
}

// round 2
// speedup vs baseline: 1.4483x; 1.4483x over previous
#include <cuda_runtime.h>
#include <math.h>
#include <stdint.h>

// Problem constants
#define NSEQ 256
#define LRES 384
#define DM   256
#define DP   128
#define NH   8
#define DHD  32
#define HD   256           // NH*DHD
#define NLROWS (NSEQ*LRES) // 98304
#define EPS 1e-5f

// -------- scratch (device globals; no allocation allowed) --------
__device__ float g_m[NLROWS * DM];        // LN(msa)
__device__ float g_qsw[LRES * HD];        // q_sw (scaled)
__device__ float g_ksw[NLROWS * HD];      // k_sw
__device__ float g_q[NLROWS * HD];        // m@Wq (unweighted)
__device__ float g_k[NLROWS * HD];        // m@Wk * 1/sqrt(DH)
__device__ float g_v[NLROWS * HD];        // m@Wv
__device__ float g_gate[NLROWS * HD];     // sigmoid(m@Wg + bg)
__device__ float g_ao[NLROWS * HD];       // attention output (pre-gate)
__device__ float g_sw[NLROWS * NH];       // seq_weight [(n*L+i)*H + h]
__device__ float g_logits[NH * LRES * LRES]; // [h][i][j]
__device__ float g_bias[NH * LRES * LRES];   // [h][i][j]
__device__ float g_attn[NH * LRES * LRES];   // [h][i][j]

// ---- tf32 helpers ----
__device__ __forceinline__ uint32_t f2tf(float x) {
    uint32_t u;
    asm("cvt.rna.tf32.f32 %0, %1;" : "=r"(u) : "f"(x));
    return u;
}
__device__ __forceinline__ void mma_tf32(float* c,
    uint32_t a0, uint32_t a1, uint32_t a2, uint32_t a3,
    uint32_t b0, uint32_t b1)
{
    asm volatile(
        "mma.sync.aligned.m16n8k8.row.col.f32.tf32.tf32.f32 "
        "{%0,%1,%2,%3},{%4,%5,%6,%7},{%8,%9},{%0,%1,%2,%3};"
        : "+f"(c[0]), "+f"(c[1]), "+f"(c[2]), "+f"(c[3])
        : "r"(a0), "r"(a1), "r"(a2), "r"(a3), "r"(b0), "r"(b1));
}

// =========================================================================
// K1: LayerNorm over msa rows (D=256). One block (256 thr) per row.
// =========================================================================
__global__ void __launch_bounds__(256) ln_msa_kernel(
    const float* __restrict__ x, const float* __restrict__ g,
    const float* __restrict__ b, float* __restrict__ out)
{
    const size_t row = blockIdx.x;
    const int t = threadIdx.x;
    float v = x[row * DM + t];
    float s = v, s2 = v * v;
    #pragma unroll
    for (int o = 16; o; o >>= 1) {
        s  += __shfl_xor_sync(0xffffffffu, s,  o);
        s2 += __shfl_xor_sync(0xffffffffu, s2, o);
    }
    __shared__ float ss[8], ss2[8], fin[2];
    const int w = t >> 5, lane = t & 31;
    if (!lane) { ss[w] = s; ss2[w] = s2; }
    __syncthreads();
    if (w == 0) {
        float a  = (lane < 8) ? ss[lane]  : 0.f;
        float a2 = (lane < 8) ? ss2[lane] : 0.f;
        #pragma unroll
        for (int o = 4; o; o >>= 1) {
            a  += __shfl_xor_sync(0xffffffffu, a,  o);
            a2 += __shfl_xor_sync(0xffffffffu, a2, o);
        }
        if (!lane) {
            float mu  = a * (1.f / DM);
            float var = a2 * (1.f / DM) - mu * mu;
            fin[0] = mu; fin[1] = rsqrtf(var + EPS);
        }
    }
    __syncthreads();
    out[row * DM + t] = (v - fin[0]) * fin[1] * g[t] + b[t];
}

// =========================================================================
// T1: tf32 tensor-core GEMM  C[M,N] = (A (*emul)) @ B, epilogue bias/scale/sigmoid.
// Block 64x64, BK=16, 256 thr = 8 warps (4m x 2n), warp tile 16x32.
// =========================================================================
__global__ void __launch_bounds__(256) tgemm_kernel(
    const float* __restrict__ A, const float* __restrict__ B, float* __restrict__ C,
    const float* __restrict__ bias, const float* __restrict__ emul,
    int M, int K, int N, float outScale, int sigm)
{
    __shared__ uint32_t As[16][72];   // [k][m]
    __shared__ uint32_t Bs[16][72];   // [k][n]
    const int tid = threadIdx.x;
    const int m0 = blockIdx.x * 64;
    const int n0 = blockIdx.y * 64;
    const int rA = tid >> 2, cA = tid & 3;   // A: row, float4-k-col
    const int rB = tid >> 4, cB = tid & 15;  // B: k-row, float4-n-col
    const int lane = tid & 31, w = tid >> 5;
    const int wm = w >> 1, wn = w & 1;
    const int gid = lane >> 2, tig = lane & 3;
    float c[4][4] = {};

    const float* Aptr = A + (size_t)(m0 + rA) * K + 4 * cA;
    const float* Eptr = emul ? emul + (size_t)(m0 + rA) * K + 4 * cA : nullptr;
    const float* Bptr = B + (size_t)rB * N + n0 + 4 * cB;

    for (int k0 = 0; k0 < K; k0 += 16) {
        float4 a4 = *(const float4*)(Aptr + k0);
        if (Eptr) {
            float4 e4 = *(const float4*)(Eptr + k0);
            a4.x *= e4.x; a4.y *= e4.y; a4.z *= e4.z; a4.w *= e4.w;
        }
        As[4*cA+0][rA] = f2tf(a4.x); As[4*cA+1][rA] = f2tf(a4.y);
        As[4*cA+2][rA] = f2tf(a4.z); As[4*cA+3][rA] = f2tf(a4.w);
        float4 b4 = *(const float4*)(Bptr + (size_t)k0 * N);
        Bs[rB][4*cB+0] = f2tf(b4.x); Bs[rB][4*cB+1] = f2tf(b4.y);
        Bs[rB][4*cB+2] = f2tf(b4.z); Bs[rB][4*cB+3] = f2tf(b4.w);
        __syncthreads();
        #pragma unroll
        for (int ks = 0; ks < 2; ks++) {
            const int kb = ks * 8;
            const uint32_t a0 = As[kb+tig  ][wm*16+gid];
            const uint32_t a1 = As[kb+tig  ][wm*16+gid+8];
            const uint32_t a2 = As[kb+tig+4][wm*16+gid];
            const uint32_t a3 = As[kb+tig+4][wm*16+gid+8];
            #pragma unroll
            for (int nt = 0; nt < 4; nt++) {
                const int nc = wn*32 + nt*8 + gid;
                mma_tf32(c[nt], a0, a1, a2, a3, Bs[kb+tig][nc], Bs[kb+tig+4][nc]);
            }
        }
        __syncthreads();
    }
    const int r0 = m0 + wm*16 + gid;
    #pragma unroll
    for (int nt = 0; nt < 4; nt++) {
        const int col = n0 + wn*32 + nt*8 + 2*tig;
        float v00 = c[nt][0], v01 = c[nt][1], v10 = c[nt][2], v11 = c[nt][3];
        if (bias) {
            const float b0v = bias[col], b1v = bias[col+1];
            v00 += b0v; v01 += b1v; v10 += b0v; v11 += b1v;
        }
        v00 *= outScale; v01 *= outScale; v10 *= outScale; v11 *= outScale;
        if (sigm) {
            v00 = 1.f/(1.f+expf(-v00)); v01 = 1.f/(1.f+expf(-v01));
            v10 = 1.f/(1.f+expf(-v10)); v11 = 1.f/(1.f+expf(-v11));
        }
        *(float2*)(C + (size_t)r0 * N + col)       = make_float2(v00, v01);
        *(float2*)(C + (size_t)(r0+8) * N + col)   = make_float2(v10, v11);
    }
}

// =========================================================================
// K3: seq-weight: softmax_n of dot(q_sw, k_sw). grid (L, H).
// =========================================================================
__global__ void __launch_bounds__(256) seqw_kernel(
    const float* __restrict__ qsw, const float* __restrict__ ksw,
    float* __restrict__ sw)
{
    const int i = blockIdx.x, h = blockIdx.y;
    const int t = threadIdx.x;            // = n
    __shared__ __align__(16) float qs[DHD];
    __shared__ float red[8];
    if (t < DHD) qs[t] = qsw[(size_t)i * HD + h * DHD + t];
    __syncthreads();
    const float* kp = ksw + ((size_t)t * LRES + i) * HD + h * DHD;
    float dot = 0.f;
    #pragma unroll
    for (int c = 0; c < 8; c++) {
        float4 k4 = *(const float4*)(kp + 4 * c);
        float4 q4 = *(const float4*)(qs + 4 * c);
        dot += k4.x * q4.x + k4.y * q4.y + k4.z * q4.z + k4.w * q4.w;
    }
    const int w = t >> 5, lane = t & 31;
    float mx = dot;
    #pragma unroll
    for (int o = 16; o; o >>= 1) mx = fmaxf(mx, __shfl_xor_sync(0xffffffffu, mx, o));
    if (!lane) red[w] = mx;
    __syncthreads();
    mx = red[0];
    #pragma unroll
    for (int x = 1; x < 8; x++) mx = fmaxf(mx, red[x]);
    const float e = expf(dot - mx);
    float s = e;
    #pragma unroll
    for (int o = 16; o; o >>= 1) s += __shfl_xor_sync(0xffffffffu, s, o);
    __syncthreads();
    if (!lane) red[w] = s;
    __syncthreads();
    float S = 0.f;
    #pragma unroll
    for (int x = 0; x < 8; x++) S += red[x];
    sw[((size_t)t * LRES + i) * NH + h] = e / S;
}

// =========================================================================
// T2: logits[h][i][j] = sum_{n,d} (q*sw)[n,i,h,d] * k[n,j,h,d], tf32 mma.
// Per head GEMM: M=N=384, K=8192 (n-loop x d=32). grid (6,6,8).
// =========================================================================
__global__ void __launch_bounds__(256) logits_tc_kernel(
    const float* __restrict__ q, const float* __restrict__ k,
    const float* __restrict__ sw, float* __restrict__ out)
{
    __shared__ uint32_t As[32][72];  // [d][i]
    __shared__ uint32_t Bs[32][72];  // [d][j]
    const int tid = threadIdx.x;
    const int i0 = blockIdx.x * 64;
    const int j0 = blockIdx.y * 64;
    const int h  = blockIdx.z;
    const int lane = tid & 31, w = tid >> 5;
    const int wm = w >> 1, wn = w & 1;
    const int gid = lane >> 2, tig = lane & 3;
    float c[4][4] = {};

    for (int n = 0; n < NSEQ; n++) {
        const size_t rowi = (size_t)n * LRES + i0;
        const size_t rowj = (size_t)n * LRES + j0;
        #pragma unroll
        for (int s = 0; s < 2; s++) {
            const int idx = tid + 256 * s;
            const int r = idx >> 3;     // 0..63
            const int cc = idx & 7;     // float4 within 32 d
            float4 a4 = *(const float4*)(q + (rowi + r) * HD + h * DHD + 4 * cc);
            const float swv = sw[(rowi + r) * NH + h];
            As[4*cc+0][r] = f2tf(a4.x * swv); As[4*cc+1][r] = f2tf(a4.y * swv);
            As[4*cc+2][r] = f2tf(a4.z * swv); As[4*cc+3][r] = f2tf(a4.w * swv);
            float4 b4 = *(const float4*)(k + (rowj + r) * HD + h * DHD + 4 * cc);
            Bs[4*cc+0][r] = f2tf(b4.x); Bs[4*cc+1][r] = f2tf(b4.y);
            Bs[4*cc+2][r] = f2tf(b4.z); Bs[4*cc+3][r] = f2tf(b4.w);
        }
        __syncthreads();
        #pragma unroll
        for (int ks = 0; ks < 4; ks++) {
            const int kb = ks * 8;
            const uint32_t a0 = As[kb+tig  ][wm*16+gid];
            const uint32_t a1 = As[kb+tig  ][wm*16+gid+8];
            const uint32_t a2 = As[kb+tig+4][wm*16+gid];
            const uint32_t a3 = As[kb+tig+4][wm*16+gid+8];
            #pragma unroll
            for (int nt = 0; nt < 4; nt++) {
                const int nc = wn*32 + nt*8 + gid;
                mma_tf32(c[nt], a0, a1, a2, a3, Bs[kb+tig][nc], Bs[kb+tig+4][nc]);
            }
        }
        __syncthreads();
    }
    const size_t ob = (size_t)h * LRES * LRES;
    const int r0 = i0 + wm*16 + gid;
    #pragma unroll
    for (int nt = 0; nt < 4; nt++) {
        const int col = j0 + wn*32 + nt*8 + 2*tig;
        *(float2*)(out + ob + (size_t)r0 * LRES + col)     = make_float2(c[nt][0], c[nt][1]);
        *(float2*)(out + ob + (size_t)(r0+8) * LRES + col) = make_float2(c[nt][2], c[nt][3]);
    }
}

// =========================================================================
// K5: pair bias: bias[h][i][j] = LN(pair[i,j,:]) @ Wb[:,h]. One warp per (i,j).
// =========================================================================
__global__ void __launch_bounds__(256) pairbias_kernel(
    const float* __restrict__ pair, const float* __restrict__ g,
    const float* __restrict__ b, const float* __restrict__ Wb,
    float* __restrict__ bias)
{
    const int w = threadIdx.x >> 5, lane = threadIdx.x & 31;
    const size_t p = (size_t)blockIdx.x * 8 + w;      // i*LRES + j
    float4 v = *(const float4*)(pair + p * DP + lane * 4);
    float s  = v.x + v.y + v.z + v.w;
    float s2 = v.x * v.x + v.y * v.y + v.z * v.z + v.w * v.w;
    #pragma unroll
    for (int o = 16; o; o >>= 1) {
        s  += __shfl_xor_sync(0xffffffffu, s,  o);
        s2 += __shfl_xor_sync(0xffffffffu, s2, o);
    }
    const float mu   = s * (1.f / DP);
    const float rstd = rsqrtf(s2 * (1.f / DP) - mu * mu + EPS);
    float xv[4] = {v.x, v.y, v.z, v.w};
    float acc[8] = {};
    #pragma unroll
    for (int c = 0; c < 4; c++) {
        const int d = lane * 4 + c;
        const float y = (xv[c] - mu) * rstd * g[d] + b[d];
        const float* wr = Wb + d * NH;
        #pragma unroll
        for (int hh = 0; hh < 8; hh++) acc[hh] = fmaf(y, wr[hh], acc[hh]);
    }
    #pragma unroll
    for (int hh = 0; hh < 8; hh++) {
        float a = acc[hh];
        #pragma unroll
        for (int o = 16; o; o >>= 1) a += __shfl_xor_sync(0xffffffffu, a, o);
        if (lane == hh) bias[(size_t)hh * LRES * LRES + p] = a;
    }
}

// =========================================================================
// K6: attn[h][i][:] = softmax_j(logits + bias). grid (L, H), 128 thr.
// =========================================================================
__global__ void __launch_bounds__(128) rowsoftmax_kernel(
    const float* __restrict__ logits, const float* __restrict__ bias,
    float* __restrict__ attn)
{
    const int i = blockIdx.x, h = blockIdx.y;
    const size_t base = ((size_t)h * LRES + i) * LRES;
    const int t = threadIdx.x;
    __shared__ float red[4];
    float x[3];
    #pragma unroll
    for (int r = 0; r < 3; r++) {
        const int j = t + r * 128;
        x[r] = logits[base + j] + bias[base + j];
    }
    float mx = fmaxf(fmaxf(x[0], x[1]), x[2]);
    #pragma unroll
    for (int o = 16; o; o >>= 1) mx = fmaxf(mx, __shfl_xor_sync(0xffffffffu, mx, o));
    const int w = t >> 5, lane = t & 31;
    if (!lane) red[w] = mx;
    __syncthreads();
    mx = fmaxf(fmaxf(red[0], red[1]), fmaxf(red[2], red[3]));
    float e[3], sum = 0.f;
    #pragma unroll
    for (int r = 0; r < 3; r++) { e[r] = expf(x[r] - mx); sum += e[r]; }
    #pragma unroll
    for (int o = 16; o; o >>= 1) sum += __shfl_xor_sync(0xffffffffu, sum, o);
    __syncthreads();
    if (!lane) red[w] = sum;
    __syncthreads();
    const float inv = 1.f / (red[0] + red[1] + red[2] + red[3]);
    #pragma unroll
    for (int r = 0; r < 3; r++) attn[base + t + r * 128] = e[r] * inv;
}

// =========================================================================
// T3: ao[n,i,h,d] = sum_j attn[h][i][j] * v[n,j,h,d], tf32 mma.
// Per head: M=384 (i), N'=8192 (n,d), K=384 (j). grid (6,128,8).
// =========================================================================
__global__ void __launch_bounds__(256) attnout_tc_kernel(
    const float* __restrict__ attn, const float* __restrict__ v,
    float* __restrict__ ao)
{
    __shared__ uint32_t As[16][72];  // [j][i]
    __shared__ uint32_t Bs[16][72];  // [j][nd]
    const int tid = threadIdx.x;
    const int i0 = blockIdx.x * 64;
    const int h  = blockIdx.z;
    const int rA = tid >> 2, cA = tid & 3;
    const int rB = tid >> 4, cB = tid & 15;
    const int nB = (blockIdx.y << 1) + (cB >> 3);
    const int dB = (cB & 7) * 4;
    const int lane = tid & 31, w = tid >> 5;
    const int wm = w >> 1, wn = w & 1;
    const int gid = lane >> 2, tig = lane & 3;
    const float* Ah = attn + (size_t)h * LRES * LRES;
    float c[4][4] = {};

    for (int j0 = 0; j0 < LRES; j0 += 16) {
        float4 a4 = *(const float4*)(Ah + (size_t)(i0 + rA) * LRES + j0 + 4 * cA);
        As[4*cA+0][rA] = f2tf(a4.x); As[4*cA+1][rA] = f2tf(a4.y);
        As[4*cA+2][rA] = f2tf(a4.z); As[4*cA+3][rA] = f2tf(a4.w);
        float4 b4 = *(const float4*)(v + ((size_t)nB * LRES + j0 + rB) * HD + h * DHD + dB);
        Bs[rB][4*cB+0] = f2tf(b4.x); Bs[rB][4*cB+1] = f2tf(b4.y);
        Bs[rB][4*cB+2] = f2tf(b4.z); Bs[rB][4*cB+3] = f2tf(b4.w);
        __syncthreads();
        #pragma unroll
        for (int ks = 0; ks < 2; ks++) {
            const int kb = ks * 8;
            const uint32_t a0 = As[kb+tig  ][wm*16+gid];
            const uint32_t a1 = As[kb+tig  ][wm*16+gid+8];
            const uint32_t a2 = As[kb+tig+4][wm*16+gid];
            const uint32_t a3 = As[kb+tig+4][wm*16+gid+8];
            #pragma unroll
            for (int nt = 0; nt < 4; nt++) {
                const int nc = wn*32 + nt*8 + gid;
                mma_tf32(c[nt], a0, a1, a2, a3, Bs[kb+tig][nc], Bs[kb+tig+4][nc]);
            }
        }
        __syncthreads();
    }
    // epilogue: local nd col = wn*32 + nt*8 + 2*tig -> n = by*2+wn, d = nt*8+2*tig
    const int nOut = (blockIdx.y << 1) + wn;
    const int r0 = i0 + wm*16 + gid;
    #pragma unroll
    for (int nt = 0; nt < 4; nt++) {
        const int d = nt*8 + 2*tig;
        float* p0 = ao + ((size_t)nOut * LRES + r0) * HD + h * DHD + d;
        float* p1 = ao + ((size_t)nOut * LRES + r0 + 8) * HD + h * DHD + d;
        *(float2*)p0 = make_float2(c[nt][0], c[nt][1]);
        *(float2*)p1 = make_float2(c[nt][2], c[nt][3]);
    }
}

// =========================================================================
// launcher
// =========================================================================
extern "C" void kernel_launch(void* const* d_in, const int* in_sizes, int n_in,
                              void* d_out, int out_size)
{
    const float* msa       = (const float*)d_in[0];
    const float* pair      = (const float*)d_in[1];
    const float* ln_msa_g  = (const float*)d_in[2];
    const float* ln_msa_b  = (const float*)d_in[3];
    const float* ln_pair_g = (const float*)d_in[4];
    const float* ln_pair_b = (const float*)d_in[5];
    const float* Wq_sw     = (const float*)d_in[6];
    const float* bq_sw     = (const float*)d_in[7];
    const float* Wk_sw     = (const float*)d_in[8];
    const float* bk_sw     = (const float*)d_in[9];
    const float* Wq        = (const float*)d_in[10];
    const float* Wk        = (const float*)d_in[11];
    const float* Wv        = (const float*)d_in[12];
    const float* Wb        = (const float*)d_in[13];
    const float* Wg        = (const float*)d_in[14];
    const float* bg        = (const float*)d_in[15];
    const float* Wo        = (const float*)d_in[16];
    const float* bo        = (const float*)d_in[17];
    float* out = (float*)d_out;

    float *m_, *qsw_, *ksw_, *q_, *k_, *v_, *gate_, *ao_, *sw_, *logits_, *bias_, *attn_;
    cudaGetSymbolAddress((void**)&m_,      g_m);
    cudaGetSymbolAddress((void**)&qsw_,    g_qsw);
    cudaGetSymbolAddress((void**)&ksw_,    g_ksw);
    cudaGetSymbolAddress((void**)&q_,      g_q);
    cudaGetSymbolAddress((void**)&k_,      g_k);
    cudaGetSymbolAddress((void**)&v_,      g_v);
    cudaGetSymbolAddress((void**)&gate_,   g_gate);
    cudaGetSymbolAddress((void**)&ao_,     g_ao);
    cudaGetSymbolAddress((void**)&sw_,     g_sw);
    cudaGetSymbolAddress((void**)&logits_, g_logits);
    cudaGetSymbolAddress((void**)&bias_,   g_bias);
    cudaGetSymbolAddress((void**)&attn_,   g_attn);

    const float scale = 0.17677669529663687f;  // 1/sqrt(32)

    // K1: LN(msa)
    ln_msa_kernel<<<NLROWS, 256>>>(msa, ln_msa_g, ln_msa_b, m_);

    // Projections (tf32 tensor cores)
    dim3 gBig(NLROWS / 64, DM / 64);
    tgemm_kernel<<<gBig, 256>>>(m_, Wk_sw, ksw_, bk_sw, nullptr, NLROWS, DM, HD, 1.f, 0);
    tgemm_kernel<<<dim3(LRES / 64, DM / 64), 256>>>(m_, Wq_sw, qsw_, bq_sw, nullptr, LRES, DM, HD, scale, 0);
    tgemm_kernel<<<gBig, 256>>>(m_, Wq, q_, nullptr, nullptr, NLROWS, DM, HD, 1.f, 0);
    tgemm_kernel<<<gBig, 256>>>(m_, Wk, k_, nullptr, nullptr, NLROWS, DM, HD, scale, 0);
    tgemm_kernel<<<gBig, 256>>>(m_, Wv, v_, nullptr, nullptr, NLROWS, DM, HD, 1.f, 0);
    tgemm_kernel<<<gBig, 256>>>(m_, Wg, gate_, bg, nullptr, NLROWS, DM, HD, 1.f, 1);

    // K3: sequence weights (softmax over n)
    seqw_kernel<<<dim3(LRES, NH), 256>>>(qsw_, ksw_, sw_);

    // T2: logits (contract n,d) tf32
    logits_tc_kernel<<<dim3(LRES / 64, LRES / 64, NH), 256>>>(q_, k_, sw_, logits_);

    // K5: pair bias
    pairbias_kernel<<<(LRES * LRES) / 8, 256>>>(pair, ln_pair_g, ln_pair_b, Wb, bias_);

    // K6: softmax over j
    rowsoftmax_kernel<<<dim3(LRES, NH), 128>>>(logits_, bias_, attn_);

    // T3: attn @ v tf32
    attnout_tc_kernel<<<dim3(LRES / 64, (NSEQ * DHD) / 64, NH), 256>>>(attn_, v_, ao_);

    // Final: (ao * gate) @ Wo + bo (tf32)
    tgemm_kernel<<<gBig, 256>>>(ao_, Wo, out, bo, gate_, NLROWS, HD, DM, 1.f, 0);
}

// round 3
// speedup vs baseline: 2.2307x; 1.5402x over previous
#include <cuda_runtime.h>
#include <math.h>
#include <stdint.h>

// Problem constants
#define NSEQ 256
#define LRES 384
#define DM   256
#define DP   128
#define NH   8
#define DHD  32
#define HD   256           // NH*DHD
#define NLROWS (NSEQ*LRES) // 98304
#define EPS 1e-5f

// -------- scratch (device globals) --------
__device__ uint32_t g_m[NLROWS * DM];        // LN(msa), tf32
__device__ float    g_qsw[LRES * HD];        // q_sw (scaled), fp32
__device__ float    g_ksw[NLROWS * HD];      // k_sw, fp32
__device__ float    g_q[NLROWS * HD];        // m@Wq, fp32
__device__ uint32_t g_qw[NLROWS * HD];       // (q * seq_weight), tf32
__device__ uint32_t g_k[NLROWS * HD];        // m@Wk * scale, tf32
__device__ uint32_t g_v[NLROWS * HD];        // m@Wv, tf32
__device__ float    g_gate[NLROWS * HD];     // sigmoid(m@Wg+bg), fp32
__device__ uint32_t g_aog[NLROWS * HD];      // (attn@v)*gate, tf32
__device__ float    g_sw[NLROWS * NH];       // seq weights
__device__ float    g_logits[NH * LRES * LRES];
__device__ float    g_bias[NH * LRES * LRES];
__device__ uint32_t g_attn[NH * LRES * LRES]; // tf32
__device__ uint32_t g_w[7 * DM * DM];        // tf32 weights: kSW,qSW,Q,K,V,G,O

// ---- helpers ----
__device__ __forceinline__ uint32_t f2tf(float x) {
    uint32_t u;
    asm("cvt.rna.tf32.f32 %0, %1;" : "=r"(u) : "f"(x));
    return u;
}
__device__ __forceinline__ void mma_tf32(float* c,
    uint32_t a0, uint32_t a1, uint32_t a2, uint32_t a3,
    uint32_t b0, uint32_t b1)
{
    asm volatile(
        "mma.sync.aligned.m16n8k8.row.col.f32.tf32.tf32.f32 "
        "{%0,%1,%2,%3},{%4,%5,%6,%7},{%8,%9},{%0,%1,%2,%3};"
        : "+f"(c[0]), "+f"(c[1]), "+f"(c[2]), "+f"(c[3])
        : "r"(a0), "r"(a1), "r"(a2), "r"(a3), "r"(b0), "r"(b1));
}
__device__ __forceinline__ void cp16(void* s, const void* g) {
    uint32_t sa = (uint32_t)__cvta_generic_to_shared(s);
    asm volatile("cp.async.cg.shared.global [%0], [%1], 16;" :: "r"(sa), "l"(g));
}
#define CP_COMMIT() asm volatile("cp.async.commit_group;")
#define CP_WAIT(n)  asm volatile("cp.async.wait_group %0;" :: "n"(n))

// =========================================================================
// K1: LayerNorm over msa rows (D=256), writes tf32.
// =========================================================================
__global__ void __launch_bounds__(256) ln_msa_kernel(
    const float* __restrict__ x, const float* __restrict__ g,
    const float* __restrict__ b, uint32_t* __restrict__ out)
{
    const size_t row = blockIdx.x;
    const int t = threadIdx.x;
    float v = x[row * DM + t];
    float s = v, s2 = v * v;
    #pragma unroll
    for (int o = 16; o; o >>= 1) {
        s  += __shfl_xor_sync(0xffffffffu, s,  o);
        s2 += __shfl_xor_sync(0xffffffffu, s2, o);
    }
    __shared__ float ss[8], ss2[8], fin[2];
    const int w = t >> 5, lane = t & 31;
    if (!lane) { ss[w] = s; ss2[w] = s2; }
    __syncthreads();
    if (w == 0) {
        float a  = (lane < 8) ? ss[lane]  : 0.f;
        float a2 = (lane < 8) ? ss2[lane] : 0.f;
        #pragma unroll
        for (int o = 4; o; o >>= 1) {
            a  += __shfl_xor_sync(0xffffffffu, a,  o);
            a2 += __shfl_xor_sync(0xffffffffu, a2, o);
        }
        if (!lane) {
            float mu  = a * (1.f / DM);
            float var = a2 * (1.f / DM) - mu * mu;
            fin[0] = mu; fin[1] = rsqrtf(var + EPS);
        }
    }
    __syncthreads();
    out[row * DM + t] = f2tf((v - fin[0]) * fin[1] * g[t] + b[t]);
}

// =========================================================================
// K0: convert 7 weight matrices (each 256x256) to tf32. grid (256, 7)
// =========================================================================
__global__ void __launch_bounds__(256) cvtw_kernel(
    const float* w0, const float* w1, const float* w2, const float* w3,
    const float* w4, const float* w5, const float* w6, uint32_t* dst)
{
    const int m = blockIdx.y;
    const int i = blockIdx.x * 256 + threadIdx.x;
    const float* src;
    switch (m) {
        case 0: src = w0; break; case 1: src = w1; break;
        case 2: src = w2; break; case 3: src = w3; break;
        case 4: src = w4; break; case 5: src = w5; break;
        default: src = w6; break;
    }
    dst[m * (DM * DM) + i] = f2tf(src[i]);
}

// =========================================================================
// T1: tf32 GEMM, all operands pre-tf32.  C[M,N] = A @ B.
// Block 128x64, BK=16, 2-stage cp.async. 8 warps = 4m x 2n of 32x32.
// Epilogue: +bias, *scale, sigmoid; OUT_TF32 selects output format.
// =========================================================================
template<bool OUT_TF32>
__global__ void __launch_bounds__(256) tgemm_kernel(
    const uint32_t* __restrict__ A, const uint32_t* __restrict__ B, void* Cv,
    const float* __restrict__ bias, int M, int K, int N, float outScale, int sigm)
{
    __shared__ uint32_t As[2][128][20];   // [stage][m][k]  (20*4B: 16B-aligned rows, conflict-free)
    __shared__ uint32_t Bs[2][16][72];    // [stage][k][n]
    const int tid = threadIdx.x;
    const int m0 = blockIdx.x * 128;
    const int n0 = blockIdx.y * 64;
    const int lane = tid & 31, w = tid >> 5;
    const int wm = w >> 1, wn = w & 1;
    const int gid = lane >> 2, tig = lane & 3;
    const int rA = tid >> 2, cA = tid & 3;    // A: 2 rows/thread pass
    const int rB = tid >> 4, cB = tid & 15;   // B: k-row, f4-col
    float acc[2][4][4] = {};

    const int T = K >> 4;
    // prologue: stage 0
    {
        const int k0 = 0;
        #pragma unroll
        for (int s = 0; s < 2; s++) {
            const int r = rA + 64 * s;
            cp16(&As[0][r][cA * 4], A + (size_t)(m0 + r) * K + k0 + cA * 4);
        }
        cp16(&Bs[0][rB][cB * 4], B + (size_t)(k0 + rB) * N + n0 + cB * 4);
        CP_COMMIT();
    }
    for (int t = 0; t < T; t++) {
        if (t + 1 < T) {
            const int k0 = (t + 1) << 4;
            const int st = (t + 1) & 1;
            #pragma unroll
            for (int s = 0; s < 2; s++) {
                const int r = rA + 64 * s;
                cp16(&As[st][r][cA * 4], A + (size_t)(m0 + r) * K + k0 + cA * 4);
            }
            cp16(&Bs[st][rB][cB * 4], B + (size_t)(k0 + rB) * N + n0 + cB * 4);
            CP_COMMIT();
            CP_WAIT(1);
        } else {
            CP_WAIT(0);
        }
        __syncthreads();
        const int st = t & 1;
        #pragma unroll
        for (int ks = 0; ks < 2; ks++) {
            const int kb = ks * 8;
            uint32_t a[2][4], bfr[4][2];
            #pragma unroll
            for (int mt = 0; mt < 2; mt++) {
                const int rm = wm * 32 + mt * 16 + gid;
                a[mt][0] = As[st][rm    ][kb + tig];
                a[mt][1] = As[st][rm + 8][kb + tig];
                a[mt][2] = As[st][rm    ][kb + tig + 4];
                a[mt][3] = As[st][rm + 8][kb + tig + 4];
            }
            #pragma unroll
            for (int nt = 0; nt < 4; nt++) {
                const int nc = wn * 32 + nt * 8 + gid;
                bfr[nt][0] = Bs[st][kb + tig    ][nc];
                bfr[nt][1] = Bs[st][kb + tig + 4][nc];
            }
            #pragma unroll
            for (int mt = 0; mt < 2; mt++)
                #pragma unroll
                for (int nt = 0; nt < 4; nt++)
                    mma_tf32(acc[mt][nt], a[mt][0], a[mt][1], a[mt][2], a[mt][3],
                             bfr[nt][0], bfr[nt][1]);
        }
        __syncthreads();
    }
    // epilogue
    #pragma unroll
    for (int mt = 0; mt < 2; mt++) {
        const int r0 = m0 + wm * 32 + mt * 16 + gid;
        #pragma unroll
        for (int nt = 0; nt < 4; nt++) {
            const int col = n0 + wn * 32 + nt * 8 + 2 * tig;
            float v00 = acc[mt][nt][0], v01 = acc[mt][nt][1];
            float v10 = acc[mt][nt][2], v11 = acc[mt][nt][3];
            if (bias) {
                const float b0v = bias[col], b1v = bias[col + 1];
                v00 += b0v; v01 += b1v; v10 += b0v; v11 += b1v;
            }
            v00 *= outScale; v01 *= outScale; v10 *= outScale; v11 *= outScale;
            if (sigm) {
                v00 = 1.f/(1.f+expf(-v00)); v01 = 1.f/(1.f+expf(-v01));
                v10 = 1.f/(1.f+expf(-v10)); v11 = 1.f/(1.f+expf(-v11));
            }
            if (OUT_TF32) {
                uint32_t* C = (uint32_t*)Cv;
                *(uint2*)(C + (size_t)r0 * N + col)       = make_uint2(f2tf(v00), f2tf(v01));
                *(uint2*)(C + (size_t)(r0+8) * N + col)   = make_uint2(f2tf(v10), f2tf(v11));
            } else {
                float* C = (float*)Cv;
                *(float2*)(C + (size_t)r0 * N + col)      = make_float2(v00, v01);
                *(float2*)(C + (size_t)(r0+8) * N + col)  = make_float2(v10, v11);
            }
        }
    }
}

// =========================================================================
// K3: seq-weight softmax over n. grid (L, H).
// =========================================================================
__global__ void __launch_bounds__(256) seqw_kernel(
    const float* __restrict__ qsw, const float* __restrict__ ksw,
    float* __restrict__ sw)
{
    const int i = blockIdx.x, h = blockIdx.y;
    const int t = threadIdx.x;            // = n
    __shared__ __align__(16) float qs[DHD];
    __shared__ float red[8];
    if (t < DHD) qs[t] = qsw[(size_t)i * HD + h * DHD + t];
    __syncthreads();
    const float* kp = ksw + ((size_t)t * LRES + i) * HD + h * DHD;
    float dot = 0.f;
    #pragma unroll
    for (int c = 0; c < 8; c++) {
        float4 k4 = *(const float4*)(kp + 4 * c);
        float4 q4 = *(const float4*)(qs + 4 * c);
        dot += k4.x * q4.x + k4.y * q4.y + k4.z * q4.z + k4.w * q4.w;
    }
    const int w = t >> 5, lane = t & 31;
    float mx = dot;
    #pragma unroll
    for (int o = 16; o; o >>= 1) mx = fmaxf(mx, __shfl_xor_sync(0xffffffffu, mx, o));
    if (!lane) red[w] = mx;
    __syncthreads();
    mx = red[0];
    #pragma unroll
    for (int x = 1; x < 8; x++) mx = fmaxf(mx, red[x]);
    const float e = expf(dot - mx);
    float s = e;
    #pragma unroll
    for (int o = 16; o; o >>= 1) s += __shfl_xor_sync(0xffffffffu, s, o);
    __syncthreads();
    if (!lane) red[w] = s;
    __syncthreads();
    float S = 0.f;
    #pragma unroll
    for (int x = 0; x < 8; x++) S += red[x];
    sw[((size_t)t * LRES + i) * NH + h] = e / S;
}

// =========================================================================
// K3b: qw = tf32(q * seq_weight) elementwise. 1 float4 per thread.
// =========================================================================
__global__ void __launch_bounds__(256) qw_kernel(
    const float* __restrict__ q, const float* __restrict__ sw,
    uint32_t* __restrict__ qw)
{
    const size_t i4 = (size_t)blockIdx.x * 256 + threadIdx.x;  // float4 index
    const size_t row = i4 >> 6;                // /64 f4 per row
    const int h = (int)((i4 >> 3) & 7);        // 8 f4 per head
    const float s = sw[row * NH + h];
    float4 v = *(const float4*)(q + i4 * 4);
    uint4 o;
    o.x = f2tf(v.x * s); o.y = f2tf(v.y * s);
    o.z = f2tf(v.z * s); o.w = f2tf(v.w * s);
    *(uint4*)(qw + i4 * 4) = o;
}

// =========================================================================
// T2: logits[h][i][j] = sum_{n,d} qw[n,i,h,d] * k[n,j,h,d].
// Per head: M=N=384, K=8192. Block 64x64, BK=32 (one n per step), 2-stage.
// 8 warps = 4m x 2n of 16x32. grid (6,6,8).
// =========================================================================
__global__ void __launch_bounds__(256) logits_tc_kernel(
    const uint32_t* __restrict__ qw, const uint32_t* __restrict__ kk,
    float* __restrict__ out)
{
    __shared__ uint32_t As[2][64][36];  // [stage][i][d]
    __shared__ uint32_t Bs[2][64][36];  // [stage][j][d]
    const int tid = threadIdx.x;
    const int i0 = blockIdx.x * 64;
    const int j0 = blockIdx.y * 64;
    const int h  = blockIdx.z;
    const int lane = tid & 31, w = tid >> 5;
    const int wm = w >> 1, wn = w & 1;
    const int gid = lane >> 2, tig = lane & 3;
    const int rL = tid >> 3, cL = tid & 7;  // loader: 32 rows/pass, f4-col of 8
    float acc[4][4] = {};

    // prologue n=0
    {
        #pragma unroll
        for (int s = 0; s < 2; s++) {
            const int r = rL + 32 * s;
            cp16(&As[0][r][cL * 4], qw + ((size_t)(i0 + r)) * HD + h * DHD + cL * 4);
            cp16(&Bs[0][r][cL * 4], kk + ((size_t)(j0 + r)) * HD + h * DHD + cL * 4);
        }
        CP_COMMIT();
    }
    for (int n = 0; n < NSEQ; n++) {
        if (n + 1 < NSEQ) {
            const int st = (n + 1) & 1;
            const size_t bi = (size_t)(n + 1) * LRES;
            #pragma unroll
            for (int s = 0; s < 2; s++) {
                const int r = rL + 32 * s;
                cp16(&As[st][r][cL * 4], qw + (bi + i0 + r) * HD + h * DHD + cL * 4);
                cp16(&Bs[st][r][cL * 4], kk + (bi + j0 + r) * HD + h * DHD + cL * 4);
            }
            CP_COMMIT();
            CP_WAIT(1);
        } else {
            CP_WAIT(0);
        }
        __syncthreads();
        const int st = n & 1;
        #pragma unroll
        for (int ks = 0; ks < 4; ks++) {
            const int kb = ks * 8;
            const int rm = wm * 16 + gid;
            const uint32_t a0 = As[st][rm    ][kb + tig];
            const uint32_t a1 = As[st][rm + 8][kb + tig];
            const uint32_t a2 = As[st][rm    ][kb + tig + 4];
            const uint32_t a3 = As[st][rm + 8][kb + tig + 4];
            #pragma unroll
            for (int nt = 0; nt < 4; nt++) {
                const int nc = wn * 32 + nt * 8 + gid;
                mma_tf32(acc[nt], a0, a1, a2, a3,
                         Bs[st][nc][kb + tig], Bs[st][nc][kb + tig + 4]);
            }
        }
        __syncthreads();
    }
    const size_t ob = (size_t)h * LRES * LRES;
    const int r0 = i0 + wm * 16 + gid;
    #pragma unroll
    for (int nt = 0; nt < 4; nt++) {
        const int col = j0 + wn * 32 + nt * 8 + 2 * tig;
        *(float2*)(out + ob + (size_t)r0 * LRES + col)     = make_float2(acc[nt][0], acc[nt][1]);
        *(float2*)(out + ob + (size_t)(r0+8) * LRES + col) = make_float2(acc[nt][2], acc[nt][3]);
    }
}

// =========================================================================
// K5: pair bias. One warp per (i,j).
// =========================================================================
__global__ void __launch_bounds__(256) pairbias_kernel(
    const float* __restrict__ pair, const float* __restrict__ g,
    const float* __restrict__ b, const float* __restrict__ Wb,
    float* __restrict__ bias)
{
    const int w = threadIdx.x >> 5, lane = threadIdx.x & 31;
    const size_t p = (size_t)blockIdx.x * 8 + w;      // i*LRES + j
    float4 v = *(const float4*)(pair + p * DP + lane * 4);
    float s  = v.x + v.y + v.z + v.w;
    float s2 = v.x * v.x + v.y * v.y + v.z * v.z + v.w * v.w;
    #pragma unroll
    for (int o = 16; o; o >>= 1) {
        s  += __shfl_xor_sync(0xffffffffu, s,  o);
        s2 += __shfl_xor_sync(0xffffffffu, s2, o);
    }
    const float mu   = s * (1.f / DP);
    const float rstd = rsqrtf(s2 * (1.f / DP) - mu * mu + EPS);
    float xv[4] = {v.x, v.y, v.z, v.w};
    float acc[8] = {};
    #pragma unroll
    for (int c = 0; c < 4; c++) {
        const int d = lane * 4 + c;
        const float y = (xv[c] - mu) * rstd * g[d] + b[d];
        const float* wr = Wb + d * NH;
        #pragma unroll
        for (int hh = 0; hh < 8; hh++) acc[hh] = fmaf(y, wr[hh], acc[hh]);
    }
    #pragma unroll
    for (int hh = 0; hh < 8; hh++) {
        float a = acc[hh];
        #pragma unroll
        for (int o = 16; o; o >>= 1) a += __shfl_xor_sync(0xffffffffu, a, o);
        if (lane == hh) bias[(size_t)hh * LRES * LRES + p] = a;
    }
}

// =========================================================================
// K6: attn = softmax_j(logits + bias), tf32 output. grid (L, H), 128 thr.
// =========================================================================
__global__ void __launch_bounds__(128) rowsoftmax_kernel(
    const float* __restrict__ logits, const float* __restrict__ bias,
    uint32_t* __restrict__ attn)
{
    const int i = blockIdx.x, h = blockIdx.y;
    const size_t base = ((size_t)h * LRES + i) * LRES;
    const int t = threadIdx.x;
    __shared__ float red[4];
    float x[3];
    #pragma unroll
    for (int r = 0; r < 3; r++) {
        const int j = t + r * 128;
        x[r] = logits[base + j] + bias[base + j];
    }
    float mx = fmaxf(fmaxf(x[0], x[1]), x[2]);
    #pragma unroll
    for (int o = 16; o; o >>= 1) mx = fmaxf(mx, __shfl_xor_sync(0xffffffffu, mx, o));
    const int w = t >> 5, lane = t & 31;
    if (!lane) red[w] = mx;
    __syncthreads();
    mx = fmaxf(fmaxf(red[0], red[1]), fmaxf(red[2], red[3]));
    float e[3], sum = 0.f;
    #pragma unroll
    for (int r = 0; r < 3; r++) { e[r] = expf(x[r] - mx); sum += e[r]; }
    #pragma unroll
    for (int o = 16; o; o >>= 1) sum += __shfl_xor_sync(0xffffffffu, sum, o);
    __syncthreads();
    if (!lane) red[w] = sum;
    __syncthreads();
    const float inv = 1.f / (red[0] + red[1] + red[2] + red[3]);
    #pragma unroll
    for (int r = 0; r < 3; r++) attn[base + t + r * 128] = f2tf(e[r] * inv);
}

// =========================================================================
// T3: aog[n,i,h,d] = tf32( gate * sum_j attn[h][i][j] * v[n,j,h,d] )
// Block 128(i) x 64(nd), BK=16(j), 2-stage. grid (3, 128, 8).
// =========================================================================
__global__ void __launch_bounds__(256) attnout_tc_kernel(
    const uint32_t* __restrict__ attn, const uint32_t* __restrict__ vv,
    const float* __restrict__ gate, uint32_t* __restrict__ aog)
{
    __shared__ uint32_t As[2][128][20];  // [stage][i][j]
    __shared__ uint32_t Bs[2][16][72];   // [stage][j][nd]
    const int tid = threadIdx.x;
    const int i0 = blockIdx.x * 128;
    const int h  = blockIdx.z;
    const int lane = tid & 31, w = tid >> 5;
    const int wm = w >> 1, wn = w & 1;
    const int gid = lane >> 2, tig = lane & 3;
    const int rA = tid >> 2, cA = tid & 3;
    const int rB = tid >> 4, cB = tid & 15;
    const int nB = (blockIdx.y << 1) + (cB >> 3);  // n for B loader
    const int dB = (cB & 7) * 4;
    const uint32_t* Ah = attn + (size_t)h * LRES * LRES;
    float acc[2][4][4] = {};

    const int T = LRES / 16;  // 24
    {
        #pragma unroll
        for (int s = 0; s < 2; s++) {
            const int r = rA + 64 * s;
            cp16(&As[0][r][cA * 4], Ah + (size_t)(i0 + r) * LRES + cA * 4);
        }
        cp16(&Bs[0][rB][cB * 4], vv + ((size_t)nB * LRES + rB) * HD + h * DHD + dB);
        CP_COMMIT();
    }
    for (int t = 0; t < T; t++) {
        if (t + 1 < T) {
            const int j0 = (t + 1) * 16;
            const int st = (t + 1) & 1;
            #pragma unroll
            for (int s = 0; s < 2; s++) {
                const int r = rA + 64 * s;
                cp16(&As[st][r][cA * 4], Ah + (size_t)(i0 + r) * LRES + j0 + cA * 4);
            }
            cp16(&Bs[st][rB][cB * 4], vv + ((size_t)nB * LRES + j0 + rB) * HD + h * DHD + dB);
            CP_COMMIT();
            CP_WAIT(1);
        } else {
            CP_WAIT(0);
        }
        __syncthreads();
        const int st = t & 1;
        #pragma unroll
        for (int ks = 0; ks < 2; ks++) {
            const int kb = ks * 8;
            uint32_t a[2][4], bfr[4][2];
            #pragma unroll
            for (int mt = 0; mt < 2; mt++) {
                const int rm = wm * 32 + mt * 16 + gid;
                a[mt][0] = As[st][rm    ][kb + tig];
                a[mt][1] = As[st][rm + 8][kb + tig];
                a[mt][2] = As[st][rm    ][kb + tig + 4];
                a[mt][3] = As[st][rm + 8][kb + tig + 4];
            }
            #pragma unroll
            for (int nt = 0; nt < 4; nt++) {
                const int nc = wn * 32 + nt * 8 + gid;
                bfr[nt][0] = Bs[st][kb + tig    ][nc];
                bfr[nt][1] = Bs[st][kb + tig + 4][nc];
            }
            #pragma unroll
            for (int mt = 0; mt < 2; mt++)
                #pragma unroll
                for (int nt = 0; nt < 4; nt++)
                    mma_tf32(acc[mt][nt], a[mt][0], a[mt][1], a[mt][2], a[mt][3],
                             bfr[nt][0], bfr[nt][1]);
        }
        __syncthreads();
    }
    // epilogue with gate multiply; col = wn*32 + nt*8 + 2tig -> n = by*2+wn, d = nt*8+2tig
    const int nOut = (blockIdx.y << 1) + wn;
    #pragma unroll
    for (int mt = 0; mt < 2; mt++) {
        const int r0 = i0 + wm * 32 + mt * 16 + gid;
        #pragma unroll
        for (int nt = 0; nt < 4; nt++) {
            const int d = nt * 8 + 2 * tig;
            const size_t p0 = ((size_t)nOut * LRES + r0) * HD + h * DHD + d;
            const size_t p1 = ((size_t)nOut * LRES + r0 + 8) * HD + h * DHD + d;
            const float2 gA = *(const float2*)(gate + p0);
            const float2 gB = *(const float2*)(gate + p1);
            *(uint2*)(aog + p0) = make_uint2(f2tf(acc[mt][nt][0] * gA.x),
                                             f2tf(acc[mt][nt][1] * gA.y));
            *(uint2*)(aog + p1) = make_uint2(f2tf(acc[mt][nt][2] * gB.x),
                                             f2tf(acc[mt][nt][3] * gB.y));
        }
    }
}

// =========================================================================
// launcher
// =========================================================================
extern "C" void kernel_launch(void* const* d_in, const int* in_sizes, int n_in,
                              void* d_out, int out_size)
{
    const float* msa       = (const float*)d_in[0];
    const float* pair      = (const float*)d_in[1];
    const float* ln_msa_g  = (const float*)d_in[2];
    const float* ln_msa_b  = (const float*)d_in[3];
    const float* ln_pair_g = (const float*)d_in[4];
    const float* ln_pair_b = (const float*)d_in[5];
    const float* Wq_sw     = (const float*)d_in[6];
    const float* bq_sw     = (const float*)d_in[7];
    const float* Wk_sw     = (const float*)d_in[8];
    const float* bk_sw     = (const float*)d_in[9];
    const float* Wq        = (const float*)d_in[10];
    const float* Wk        = (const float*)d_in[11];
    const float* Wv        = (const float*)d_in[12];
    const float* Wb        = (const float*)d_in[13];
    const float* Wg        = (const float*)d_in[14];
    const float* bg        = (const float*)d_in[15];
    const float* Wo        = (const float*)d_in[16];
    const float* bo        = (const float*)d_in[17];
    float* out = (float*)d_out;

    uint32_t *m_, *qw_, *k_, *v_, *aog_, *attn_, *w_;
    float *qsw_, *ksw_, *q_, *gate_, *sw_, *logits_, *bias_;
    cudaGetSymbolAddress((void**)&m_,      g_m);
    cudaGetSymbolAddress((void**)&qsw_,    g_qsw);
    cudaGetSymbolAddress((void**)&ksw_,    g_ksw);
    cudaGetSymbolAddress((void**)&q_,      g_q);
    cudaGetSymbolAddress((void**)&qw_,     g_qw);
    cudaGetSymbolAddress((void**)&k_,      g_k);
    cudaGetSymbolAddress((void**)&v_,      g_v);
    cudaGetSymbolAddress((void**)&gate_,   g_gate);
    cudaGetSymbolAddress((void**)&aog_,    g_aog);
    cudaGetSymbolAddress((void**)&sw_,     g_sw);
    cudaGetSymbolAddress((void**)&logits_, g_logits);
    cudaGetSymbolAddress((void**)&bias_,   g_bias);
    cudaGetSymbolAddress((void**)&attn_,   g_attn);
    cudaGetSymbolAddress((void**)&w_,      g_w);

    const float scale = 0.17677669529663687f;  // 1/sqrt(32)
    const int WSZ = DM * DM;  // 65536
    const uint32_t *WkSW = w_ + 0*WSZ, *WqSW = w_ + 1*WSZ, *WQ = w_ + 2*WSZ,
                   *WK = w_ + 3*WSZ, *WV = w_ + 4*WSZ, *WG = w_ + 5*WSZ,
                   *WO = w_ + 6*WSZ;

    // K0/K1: convert weights + LN(msa) to tf32
    cvtw_kernel<<<dim3(WSZ / 256, 7), 256>>>(Wk_sw, Wq_sw, Wq, Wk, Wv, Wg, Wo, w_);
    ln_msa_kernel<<<NLROWS, 256>>>(msa, ln_msa_g, ln_msa_b, m_);

    // projections (tf32 tc, cp.async)
    dim3 gBig(NLROWS / 128, HD / 64);
    tgemm_kernel<false><<<gBig, 256>>>(m_, WkSW, ksw_, bk_sw, NLROWS, DM, HD, 1.f, 0);
    tgemm_kernel<false><<<dim3(LRES / 128, HD / 64), 256>>>(m_, WqSW, qsw_, bq_sw, LRES, DM, HD, scale, 0);
    tgemm_kernel<false><<<gBig, 256>>>(m_, WQ, q_, nullptr, NLROWS, DM, HD, 1.f, 0);
    tgemm_kernel<true ><<<gBig, 256>>>(m_, WK, k_, nullptr, NLROWS, DM, HD, scale, 0);
    tgemm_kernel<true ><<<gBig, 256>>>(m_, WV, v_, nullptr, NLROWS, DM, HD, 1.f, 0);
    tgemm_kernel<false><<<gBig, 256>>>(m_, WG, gate_, bg, NLROWS, DM, HD, 1.f, 1);

    // seq weights + weighted q
    seqw_kernel<<<dim3(LRES, NH), 256>>>(qsw_, ksw_, sw_);
    qw_kernel<<<(NLROWS * HD / 4) / 256, 256>>>(q_, sw_, qw_);

    // logits
    logits_tc_kernel<<<dim3(LRES / 64, LRES / 64, NH), 256>>>(qw_, k_, logits_);

    // pair bias + softmax
    pairbias_kernel<<<(LRES * LRES) / 8, 256>>>(pair, ln_pair_g, ln_pair_b, Wb, bias_);
    rowsoftmax_kernel<<<dim3(LRES, NH), 128>>>(logits_, bias_, attn_);

    // attn @ v (with gate fused)
    attnout_tc_kernel<<<dim3(LRES / 128, (NSEQ * DHD) / 64, NH), 256>>>(attn_, v_, gate_, aog_);

    // final: aog @ Wo + bo
    tgemm_kernel<false><<<gBig, 256>>>(aog_, WO, out, bo, NLROWS, HD, DM, 1.f, 0);
}

// round 4
// speedup vs baseline: 2.3112x; 1.0361x over previous
#include <cuda_runtime.h>
#include <math.h>
#include <stdint.h>

// Problem constants
#define NSEQ 256
#define LRES 384
#define DM   256
#define DP   128
#define NH   8
#define DHD  32
#define HD   256           // NH*DHD
#define NLROWS (NSEQ*LRES) // 98304
#define EPS 1e-5f
#define NWIDE 1280         // 5 fused projection outputs

// -------- scratch (device globals) --------
__device__ uint32_t g_m[NLROWS * DM];        // LN(msa), tf32
__device__ float    g_qsw[LRES * HD];        // q_sw (scaled), fp32
__device__ float    g_ksw[NLROWS * HD];      // k_sw, fp32
__device__ float    g_q[NLROWS * HD];        // m@Wq, fp32
__device__ uint32_t g_qw[NLROWS * HD];       // (q * seq_weight), tf32
__device__ uint32_t g_k[NLROWS * HD];        // m@Wk * scale, tf32
__device__ uint32_t g_v[NLROWS * HD];        // m@Wv, tf32
__device__ float    g_gate[NLROWS * HD];     // sigmoid(m@Wg+bg), fp32
__device__ uint32_t g_aog[NLROWS * HD];      // (attn@v)*gate, tf32
__device__ float    g_sw[NLROWS * NH];       // seq weights
__device__ float    g_logits[NH * LRES * LRES];
__device__ float    g_bias[NH * LRES * LRES];
__device__ uint32_t g_attn[NH * LRES * LRES]; // tf32
__device__ uint32_t g_wpack[DM * NWIDE];      // packed tf32 [k][kSW|Q|K|V|G]
__device__ uint32_t g_w2[2 * DM * DM];        // tf32: qSW, O

// ---- helpers ----
__device__ __forceinline__ uint32_t f2tf(float x) {
    uint32_t u;
    asm("cvt.rna.tf32.f32 %0, %1;" : "=r"(u) : "f"(x));
    return u;
}
__device__ __forceinline__ void mma_tf32(float* c,
    uint32_t a0, uint32_t a1, uint32_t a2, uint32_t a3,
    uint32_t b0, uint32_t b1)
{
    asm volatile(
        "mma.sync.aligned.m16n8k8.row.col.f32.tf32.tf32.f32 "
        "{%0,%1,%2,%3},{%4,%5,%6,%7},{%8,%9},{%0,%1,%2,%3};"
        : "+f"(c[0]), "+f"(c[1]), "+f"(c[2]), "+f"(c[3])
        : "r"(a0), "r"(a1), "r"(a2), "r"(a3), "r"(b0), "r"(b1));
}
__device__ __forceinline__ void cp16(void* s, const void* g) {
    uint32_t sa = (uint32_t)__cvta_generic_to_shared(s);
    asm volatile("cp.async.cg.shared.global [%0], [%1], 16;" :: "r"(sa), "l"(g));
}
#define CP_COMMIT() asm volatile("cp.async.commit_group;")
#define CP_WAIT(n)  asm volatile("cp.async.wait_group %0;" :: "n"(n))

// =========================================================================
// K0a: build packed tf32 weight [k][1280]: segs kSW,Q,K,V,G. grid 1280x256.
// =========================================================================
__global__ void __launch_bounds__(256) cvt_pack_kernel(
    const float* w0, const float* w1, const float* w2, const float* w3,
    const float* w4, uint32_t* dst)
{
    const int idx = blockIdx.x * 256 + threadIdx.x;   // < 256*1280
    const int k = idx / NWIDE, c = idx % NWIDE;
    const int seg = c >> 8, cc = c & 255;
    const float* src;
    switch (seg) {
        case 0: src = w0; break; case 1: src = w1; break;
        case 2: src = w2; break; case 3: src = w3; break;
        default: src = w4; break;
    }
    dst[idx] = f2tf(src[k * DM + cc]);
}
// K0b: qSW + O weights to tf32. grid (256, 2)
__global__ void __launch_bounds__(256) cvt2_kernel(
    const float* w0, const float* w1, uint32_t* dst)
{
    const int m = blockIdx.y;
    const int i = blockIdx.x * 256 + threadIdx.x;
    dst[m * (DM * DM) + i] = f2tf(m == 0 ? w0[i] : w1[i]);
}

// =========================================================================
// K1: LayerNorm over msa rows (D=256), writes tf32.
// =========================================================================
__global__ void __launch_bounds__(256) ln_msa_kernel(
    const float* __restrict__ x, const float* __restrict__ g,
    const float* __restrict__ b, uint32_t* __restrict__ out)
{
    const size_t row = blockIdx.x;
    const int t = threadIdx.x;
    float v = x[row * DM + t];
    float s = v, s2 = v * v;
    #pragma unroll
    for (int o = 16; o; o >>= 1) {
        s  += __shfl_xor_sync(0xffffffffu, s,  o);
        s2 += __shfl_xor_sync(0xffffffffu, s2, o);
    }
    __shared__ float ss[8], ss2[8], fin[2];
    const int w = t >> 5, lane = t & 31;
    if (!lane) { ss[w] = s; ss2[w] = s2; }
    __syncthreads();
    if (w == 0) {
        float a  = (lane < 8) ? ss[lane]  : 0.f;
        float a2 = (lane < 8) ? ss2[lane] : 0.f;
        #pragma unroll
        for (int o = 4; o; o >>= 1) {
            a  += __shfl_xor_sync(0xffffffffu, a,  o);
            a2 += __shfl_xor_sync(0xffffffffu, a2, o);
        }
        if (!lane) {
            float mu  = a * (1.f / DM);
            float var = a2 * (1.f / DM) - mu * mu;
            fin[0] = mu; fin[1] = rsqrtf(var + EPS);
        }
    }
    __syncthreads();
    out[row * DM + t] = f2tf((v - fin[0]) * fin[1] * g[t] + b[t]);
}

// =========================================================================
// W1: wide tf32 GEMM. Block 128x128, BK=16, 2-stage cp.async.
// 8 warps = 4m x 2n of 32x64 tiles. K=256.
// MODE 0: fused 5-segment projection epilogue (Nld=1280).
// MODE 1: plain fp32 out: C = (acc + bias) * scale  (Nld = N of B/C).
// =========================================================================
template<int MODE>
__global__ void __launch_bounds__(256, 2) wgemm_kernel(
    const uint32_t* __restrict__ A, const uint32_t* __restrict__ B,
    int M, int K, int Nld,
    float* __restrict__ ksw, float* __restrict__ qf,
    uint32_t* __restrict__ ktf, uint32_t* __restrict__ vtf,
    float* __restrict__ gatef,
    const float* __restrict__ bias0, const float* __restrict__ bias1,
    float scaleArg, float* __restrict__ C)
{
    __shared__ uint32_t As[2][128][20];
    __shared__ uint32_t Bs[2][16][136];
    const int tid = threadIdx.x;
    const int m0 = blockIdx.x * 128;
    const int n0 = blockIdx.y * 128;
    const int lane = tid & 31, w = tid >> 5;
    const int wm = w >> 1, wn = w & 1;
    const int gid = lane >> 2, tig = lane & 3;
    const int rA = tid >> 2, cA = tid & 3;
    const int rB = tid >> 4, cB = tid & 15;
    float acc[2][8][4] = {};

    const int T = K >> 4;
    {
        #pragma unroll
        for (int s = 0; s < 2; s++) {
            const int r = rA + 64 * s;
            cp16(&As[0][r][cA * 4], A + (size_t)(m0 + r) * K + cA * 4);
        }
        #pragma unroll
        for (int p = 0; p < 2; p++)
            cp16(&Bs[0][rB][(cB + 16 * p) * 4],
                 B + (size_t)rB * Nld + n0 + (cB + 16 * p) * 4);
        CP_COMMIT();
    }
    for (int t = 0; t < T; t++) {
        if (t + 1 < T) {
            const int k0 = (t + 1) << 4;
            const int st = (t + 1) & 1;
            #pragma unroll
            for (int s = 0; s < 2; s++) {
                const int r = rA + 64 * s;
                cp16(&As[st][r][cA * 4], A + (size_t)(m0 + r) * K + k0 + cA * 4);
            }
            #pragma unroll
            for (int p = 0; p < 2; p++)
                cp16(&Bs[st][rB][(cB + 16 * p) * 4],
                     B + (size_t)(k0 + rB) * Nld + n0 + (cB + 16 * p) * 4);
            CP_COMMIT();
            CP_WAIT(1);
        } else {
            CP_WAIT(0);
        }
        __syncthreads();
        const int st = t & 1;
        #pragma unroll
        for (int ks = 0; ks < 2; ks++) {
            const int kb = ks * 8;
            uint32_t a[2][4], bfr[8][2];
            #pragma unroll
            for (int mt = 0; mt < 2; mt++) {
                const int rm = wm * 32 + mt * 16 + gid;
                a[mt][0] = As[st][rm    ][kb + tig];
                a[mt][1] = As[st][rm + 8][kb + tig];
                a[mt][2] = As[st][rm    ][kb + tig + 4];
                a[mt][3] = As[st][rm + 8][kb + tig + 4];
            }
            #pragma unroll
            for (int nt = 0; nt < 8; nt++) {
                const int nc = wn * 64 + nt * 8 + gid;
                bfr[nt][0] = Bs[st][kb + tig    ][nc];
                bfr[nt][1] = Bs[st][kb + tig + 4][nc];
            }
            #pragma unroll
            for (int mt = 0; mt < 2; mt++)
                #pragma unroll
                for (int nt = 0; nt < 8; nt++)
                    mma_tf32(acc[mt][nt], a[mt][0], a[mt][1], a[mt][2], a[mt][3],
                             bfr[nt][0], bfr[nt][1]);
        }
        __syncthreads();
    }
    // epilogue
    const int seg = (MODE == 0) ? (blockIdx.y >> 1) : 0;
    #pragma unroll
    for (int mt = 0; mt < 2; mt++) {
        const int r0 = m0 + wm * 32 + mt * 16 + gid;
        #pragma unroll
        for (int nt = 0; nt < 8; nt++) {
            const int col = n0 + wn * 64 + nt * 8 + 2 * tig;
            float v00 = acc[mt][nt][0], v01 = acc[mt][nt][1];
            float v10 = acc[mt][nt][2], v11 = acc[mt][nt][3];
            if (MODE == 0) {
                const int cc = col & 255;
                const size_t p0 = (size_t)r0 * HD + cc;
                const size_t p1 = (size_t)(r0 + 8) * HD + cc;
                switch (seg) {
                    case 0: {  // ksw = acc + bk_sw, fp32
                        const float b0 = bias0[cc], b1 = bias0[cc + 1];
                        *(float2*)(ksw + p0) = make_float2(v00 + b0, v01 + b1);
                        *(float2*)(ksw + p1) = make_float2(v10 + b0, v11 + b1);
                        break;
                    }
                    case 1: {  // q, fp32
                        *(float2*)(qf + p0) = make_float2(v00, v01);
                        *(float2*)(qf + p1) = make_float2(v10, v11);
                        break;
                    }
                    case 2: {  // k * scale, tf32
                        *(uint2*)(ktf + p0) = make_uint2(f2tf(v00 * scaleArg), f2tf(v01 * scaleArg));
                        *(uint2*)(ktf + p1) = make_uint2(f2tf(v10 * scaleArg), f2tf(v11 * scaleArg));
                        break;
                    }
                    case 3: {  // v, tf32
                        *(uint2*)(vtf + p0) = make_uint2(f2tf(v00), f2tf(v01));
                        *(uint2*)(vtf + p1) = make_uint2(f2tf(v10), f2tf(v11));
                        break;
                    }
                    default: { // gate = sigmoid(acc + bg), fp32
                        const float b0 = bias1[cc], b1 = bias1[cc + 1];
                        *(float2*)(gatef + p0) = make_float2(1.f/(1.f+expf(-(v00+b0))),
                                                             1.f/(1.f+expf(-(v01+b1))));
                        *(float2*)(gatef + p1) = make_float2(1.f/(1.f+expf(-(v10+b0))),
                                                             1.f/(1.f+expf(-(v11+b1))));
                        break;
                    }
                }
            } else {
                const float b0 = bias0 ? bias0[col] : 0.f;
                const float b1 = bias0 ? bias0[col + 1] : 0.f;
                *(float2*)(C + (size_t)r0 * Nld + col) =
                    make_float2((v00 + b0) * scaleArg, (v01 + b1) * scaleArg);
                *(float2*)(C + (size_t)(r0 + 8) * Nld + col) =
                    make_float2((v10 + b0) * scaleArg, (v11 + b1) * scaleArg);
            }
        }
    }
}

// =========================================================================
// K3: seq-weight softmax over n. grid (L, H).
// =========================================================================
__global__ void __launch_bounds__(256) seqw_kernel(
    const float* __restrict__ qsw, const float* __restrict__ ksw,
    float* __restrict__ sw)
{
    const int i = blockIdx.x, h = blockIdx.y;
    const int t = threadIdx.x;            // = n
    __shared__ __align__(16) float qs[DHD];
    __shared__ float red[8];
    if (t < DHD) qs[t] = qsw[(size_t)i * HD + h * DHD + t];
    __syncthreads();
    const float* kp = ksw + ((size_t)t * LRES + i) * HD + h * DHD;
    float dot = 0.f;
    #pragma unroll
    for (int c = 0; c < 8; c++) {
        float4 k4 = *(const float4*)(kp + 4 * c);
        float4 q4 = *(const float4*)(qs + 4 * c);
        dot += k4.x * q4.x + k4.y * q4.y + k4.z * q4.z + k4.w * q4.w;
    }
    const int w = t >> 5, lane = t & 31;
    float mx = dot;
    #pragma unroll
    for (int o = 16; o; o >>= 1) mx = fmaxf(mx, __shfl_xor_sync(0xffffffffu, mx, o));
    if (!lane) red[w] = mx;
    __syncthreads();
    mx = red[0];
    #pragma unroll
    for (int x = 1; x < 8; x++) mx = fmaxf(mx, red[x]);
    const float e = expf(dot - mx);
    float s = e;
    #pragma unroll
    for (int o = 16; o; o >>= 1) s += __shfl_xor_sync(0xffffffffu, s, o);
    __syncthreads();
    if (!lane) red[w] = s;
    __syncthreads();
    float S = 0.f;
    #pragma unroll
    for (int x = 0; x < 8; x++) S += red[x];
    sw[((size_t)t * LRES + i) * NH + h] = e / S;
}

// =========================================================================
// K3b: qw = tf32(q * seq_weight) elementwise.
// =========================================================================
__global__ void __launch_bounds__(256) qw_kernel(
    const float* __restrict__ q, const float* __restrict__ sw,
    uint32_t* __restrict__ qw)
{
    const size_t i4 = (size_t)blockIdx.x * 256 + threadIdx.x;  // float4 index
    const size_t row = i4 >> 6;
    const int h = (int)((i4 >> 3) & 7);
    const float s = sw[row * NH + h];
    float4 v = *(const float4*)(q + i4 * 4);
    uint4 o;
    o.x = f2tf(v.x * s); o.y = f2tf(v.y * s);
    o.z = f2tf(v.z * s); o.w = f2tf(v.w * s);
    *(uint4*)(qw + i4 * 4) = o;
}

// =========================================================================
// T2: logits[h][i][j] = sum_{n,d} qw[n,i,h,d] * k[n,j,h,d].
// Block 64x64, BK=32 (one n/step), 2-stage. grid (6,6,8).
// =========================================================================
__global__ void __launch_bounds__(256) logits_tc_kernel(
    const uint32_t* __restrict__ qw, const uint32_t* __restrict__ kk,
    float* __restrict__ out)
{
    __shared__ uint32_t As[2][64][36];
    __shared__ uint32_t Bs[2][64][36];
    const int tid = threadIdx.x;
    const int i0 = blockIdx.x * 64;
    const int j0 = blockIdx.y * 64;
    const int h  = blockIdx.z;
    const int lane = tid & 31, w = tid >> 5;
    const int wm = w >> 1, wn = w & 1;
    const int gid = lane >> 2, tig = lane & 3;
    const int rL = tid >> 3, cL = tid & 7;
    float acc[4][4] = {};

    {
        #pragma unroll
        for (int s = 0; s < 2; s++) {
            const int r = rL + 32 * s;
            cp16(&As[0][r][cL * 4], qw + ((size_t)(i0 + r)) * HD + h * DHD + cL * 4);
            cp16(&Bs[0][r][cL * 4], kk + ((size_t)(j0 + r)) * HD + h * DHD + cL * 4);
        }
        CP_COMMIT();
    }
    for (int n = 0; n < NSEQ; n++) {
        if (n + 1 < NSEQ) {
            const int st = (n + 1) & 1;
            const size_t bi = (size_t)(n + 1) * LRES;
            #pragma unroll
            for (int s = 0; s < 2; s++) {
                const int r = rL + 32 * s;
                cp16(&As[st][r][cL * 4], qw + (bi + i0 + r) * HD + h * DHD + cL * 4);
                cp16(&Bs[st][r][cL * 4], kk + (bi + j0 + r) * HD + h * DHD + cL * 4);
            }
            CP_COMMIT();
            CP_WAIT(1);
        } else {
            CP_WAIT(0);
        }
        __syncthreads();
        const int st = n & 1;
        #pragma unroll
        for (int ks = 0; ks < 4; ks++) {
            const int kb = ks * 8;
            const int rm = wm * 16 + gid;
            const uint32_t a0 = As[st][rm    ][kb + tig];
            const uint32_t a1 = As[st][rm + 8][kb + tig];
            const uint32_t a2 = As[st][rm    ][kb + tig + 4];
            const uint32_t a3 = As[st][rm + 8][kb + tig + 4];
            #pragma unroll
            for (int nt = 0; nt < 4; nt++) {
                const int nc = wn * 32 + nt * 8 + gid;
                mma_tf32(acc[nt], a0, a1, a2, a3,
                         Bs[st][nc][kb + tig], Bs[st][nc][kb + tig + 4]);
            }
        }
        __syncthreads();
    }
    const size_t ob = (size_t)h * LRES * LRES;
    const int r0 = i0 + wm * 16 + gid;
    #pragma unroll
    for (int nt = 0; nt < 4; nt++) {
        const int col = j0 + wn * 32 + nt * 8 + 2 * tig;
        *(float2*)(out + ob + (size_t)r0 * LRES + col)     = make_float2(acc[nt][0], acc[nt][1]);
        *(float2*)(out + ob + (size_t)(r0+8) * LRES + col) = make_float2(acc[nt][2], acc[nt][3]);
    }
}

// =========================================================================
// K5: pair bias. One warp per (i,j).
// =========================================================================
__global__ void __launch_bounds__(256) pairbias_kernel(
    const float* __restrict__ pair, const float* __restrict__ g,
    const float* __restrict__ b, const float* __restrict__ Wb,
    float* __restrict__ bias)
{
    const int w = threadIdx.x >> 5, lane = threadIdx.x & 31;
    const size_t p = (size_t)blockIdx.x * 8 + w;
    float4 v = *(const float4*)(pair + p * DP + lane * 4);
    float s  = v.x + v.y + v.z + v.w;
    float s2 = v.x * v.x + v.y * v.y + v.z * v.z + v.w * v.w;
    #pragma unroll
    for (int o = 16; o; o >>= 1) {
        s  += __shfl_xor_sync(0xffffffffu, s,  o);
        s2 += __shfl_xor_sync(0xffffffffu, s2, o);
    }
    const float mu   = s * (1.f / DP);
    const float rstd = rsqrtf(s2 * (1.f / DP) - mu * mu + EPS);
    float xv[4] = {v.x, v.y, v.z, v.w};
    float acc[8] = {};
    #pragma unroll
    for (int c = 0; c < 4; c++) {
        const int d = lane * 4 + c;
        const float y = (xv[c] - mu) * rstd * g[d] + b[d];
        const float* wr = Wb + d * NH;
        #pragma unroll
        for (int hh = 0; hh < 8; hh++) acc[hh] = fmaf(y, wr[hh], acc[hh]);
    }
    #pragma unroll
    for (int hh = 0; hh < 8; hh++) {
        float a = acc[hh];
        #pragma unroll
        for (int o = 16; o; o >>= 1) a += __shfl_xor_sync(0xffffffffu, a, o);
        if (lane == hh) bias[(size_t)hh * LRES * LRES + p] = a;
    }
}

// =========================================================================
// K6: attn = softmax_j(logits + bias), tf32 output. grid (L, H), 128 thr.
// =========================================================================
__global__ void __launch_bounds__(128) rowsoftmax_kernel(
    const float* __restrict__ logits, const float* __restrict__ bias,
    uint32_t* __restrict__ attn)
{
    const int i = blockIdx.x, h = blockIdx.y;
    const size_t base = ((size_t)h * LRES + i) * LRES;
    const int t = threadIdx.x;
    __shared__ float red[4];
    float x[3];
    #pragma unroll
    for (int r = 0; r < 3; r++) {
        const int j = t + r * 128;
        x[r] = logits[base + j] + bias[base + j];
    }
    float mx = fmaxf(fmaxf(x[0], x[1]), x[2]);
    #pragma unroll
    for (int o = 16; o; o >>= 1) mx = fmaxf(mx, __shfl_xor_sync(0xffffffffu, mx, o));
    const int w = t >> 5, lane = t & 31;
    if (!lane) red[w] = mx;
    __syncthreads();
    mx = fmaxf(fmaxf(red[0], red[1]), fmaxf(red[2], red[3]));
    float e[3], sum = 0.f;
    #pragma unroll
    for (int r = 0; r < 3; r++) { e[r] = expf(x[r] - mx); sum += e[r]; }
    #pragma unroll
    for (int o = 16; o; o >>= 1) sum += __shfl_xor_sync(0xffffffffu, sum, o);
    __syncthreads();
    if (!lane) red[w] = sum;
    __syncthreads();
    const float inv = 1.f / (red[0] + red[1] + red[2] + red[3]);
    #pragma unroll
    for (int r = 0; r < 3; r++) attn[base + t + r * 128] = f2tf(e[r] * inv);
}

// =========================================================================
// T3: aog[n,i,h,d] = tf32( gate * sum_j attn[h][i][j] * v[n,j,h,d] )
// Block 128(i) x 64(nd), BK=16(j), 2-stage. grid (3, 128, 8).
// =========================================================================
__global__ void __launch_bounds__(256) attnout_tc_kernel(
    const uint32_t* __restrict__ attn, const uint32_t* __restrict__ vv,
    const float* __restrict__ gate, uint32_t* __restrict__ aog)
{
    __shared__ uint32_t As[2][128][20];
    __shared__ uint32_t Bs[2][16][72];
    const int tid = threadIdx.x;
    const int i0 = blockIdx.x * 128;
    const int h  = blockIdx.z;
    const int lane = tid & 31, w = tid >> 5;
    const int wm = w >> 1, wn = w & 1;
    const int gid = lane >> 2, tig = lane & 3;
    const int rA = tid >> 2, cA = tid & 3;
    const int rB = tid >> 4, cB = tid & 15;
    const int nB = (blockIdx.y << 1) + (cB >> 3);
    const int dB = (cB & 7) * 4;
    const uint32_t* Ah = attn + (size_t)h * LRES * LRES;
    float acc[2][4][4] = {};

    const int T = LRES / 16;  // 24
    {
        #pragma unroll
        for (int s = 0; s < 2; s++) {
            const int r = rA + 64 * s;
            cp16(&As[0][r][cA * 4], Ah + (size_t)(i0 + r) * LRES + cA * 4);
        }
        cp16(&Bs[0][rB][cB * 4], vv + ((size_t)nB * LRES + rB) * HD + h * DHD + dB);
        CP_COMMIT();
    }
    for (int t = 0; t < T; t++) {
        if (t + 1 < T) {
            const int j0 = (t + 1) * 16;
            const int st = (t + 1) & 1;
            #pragma unroll
            for (int s = 0; s < 2; s++) {
                const int r = rA + 64 * s;
                cp16(&As[st][r][cA * 4], Ah + (size_t)(i0 + r) * LRES + j0 + cA * 4);
            }
            cp16(&Bs[st][rB][cB * 4], vv + ((size_t)nB * LRES + j0 + rB) * HD + h * DHD + dB);
            CP_COMMIT();
            CP_WAIT(1);
        } else {
            CP_WAIT(0);
        }
        __syncthreads();
        const int st = t & 1;
        #pragma unroll
        for (int ks = 0; ks < 2; ks++) {
            const int kb = ks * 8;
            uint32_t a[2][4], bfr[4][2];
            #pragma unroll
            for (int mt = 0; mt < 2; mt++) {
                const int rm = wm * 32 + mt * 16 + gid;
                a[mt][0] = As[st][rm    ][kb + tig];
                a[mt][1] = As[st][rm + 8][kb + tig];
                a[mt][2] = As[st][rm    ][kb + tig + 4];
                a[mt][3] = As[st][rm + 8][kb + tig + 4];
            }
            #pragma unroll
            for (int nt = 0; nt < 4; nt++) {
                const int nc = wn * 32 + nt * 8 + gid;
                bfr[nt][0] = Bs[st][kb + tig    ][nc];
                bfr[nt][1] = Bs[st][kb + tig + 4][nc];
            }
            #pragma unroll
            for (int mt = 0; mt < 2; mt++)
                #pragma unroll
                for (int nt = 0; nt < 4; nt++)
                    mma_tf32(acc[mt][nt], a[mt][0], a[mt][1], a[mt][2], a[mt][3],
                             bfr[nt][0], bfr[nt][1]);
        }
        __syncthreads();
    }
    const int nOut = (blockIdx.y << 1) + wn;
    #pragma unroll
    for (int mt = 0; mt < 2; mt++) {
        const int r0 = i0 + wm * 32 + mt * 16 + gid;
        #pragma unroll
        for (int nt = 0; nt < 4; nt++) {
            const int d = nt * 8 + 2 * tig;
            const size_t p0 = ((size_t)nOut * LRES + r0) * HD + h * DHD + d;
            const size_t p1 = ((size_t)nOut * LRES + r0 + 8) * HD + h * DHD + d;
            const float2 gA = *(const float2*)(gate + p0);
            const float2 gB = *(const float2*)(gate + p1);
            *(uint2*)(aog + p0) = make_uint2(f2tf(acc[mt][nt][0] * gA.x),
                                             f2tf(acc[mt][nt][1] * gA.y));
            *(uint2*)(aog + p1) = make_uint2(f2tf(acc[mt][nt][2] * gB.x),
                                             f2tf(acc[mt][nt][3] * gB.y));
        }
    }
}

// =========================================================================
// launcher
// =========================================================================
extern "C" void kernel_launch(void* const* d_in, const int* in_sizes, int n_in,
                              void* d_out, int out_size)
{
    const float* msa       = (const float*)d_in[0];
    const float* pair      = (const float*)d_in[1];
    const float* ln_msa_g  = (const float*)d_in[2];
    const float* ln_msa_b  = (const float*)d_in[3];
    const float* ln_pair_g = (const float*)d_in[4];
    const float* ln_pair_b = (const float*)d_in[5];
    const float* Wq_sw     = (const float*)d_in[6];
    const float* bq_sw     = (const float*)d_in[7];
    const float* Wk_sw     = (const float*)d_in[8];
    const float* bk_sw     = (const float*)d_in[9];
    const float* Wq        = (const float*)d_in[10];
    const float* Wk        = (const float*)d_in[11];
    const float* Wv        = (const float*)d_in[12];
    const float* Wb        = (const float*)d_in[13];
    const float* Wg        = (const float*)d_in[14];
    const float* bg        = (const float*)d_in[15];
    const float* Wo        = (const float*)d_in[16];
    const float* bo        = (const float*)d_in[17];
    float* out = (float*)d_out;

    uint32_t *m_, *qw_, *k_, *v_, *aog_, *attn_, *wpack_, *w2_;
    float *qsw_, *ksw_, *q_, *gate_, *sw_, *logits_, *bias_;
    cudaGetSymbolAddress((void**)&m_,      g_m);
    cudaGetSymbolAddress((void**)&qsw_,    g_qsw);
    cudaGetSymbolAddress((void**)&ksw_,    g_ksw);
    cudaGetSymbolAddress((void**)&q_,      g_q);
    cudaGetSymbolAddress((void**)&qw_,     g_qw);
    cudaGetSymbolAddress((void**)&k_,      g_k);
    cudaGetSymbolAddress((void**)&v_,      g_v);
    cudaGetSymbolAddress((void**)&gate_,   g_gate);
    cudaGetSymbolAddress((void**)&aog_,    g_aog);
    cudaGetSymbolAddress((void**)&sw_,     g_sw);
    cudaGetSymbolAddress((void**)&logits_, g_logits);
    cudaGetSymbolAddress((void**)&bias_,   g_bias);
    cudaGetSymbolAddress((void**)&attn_,   g_attn);
    cudaGetSymbolAddress((void**)&wpack_,  g_wpack);
    cudaGetSymbolAddress((void**)&w2_,     g_w2);

    const float scale = 0.17677669529663687f;  // 1/sqrt(32)
    const uint32_t *WqSW = w2_, *WO = w2_ + DM * DM;

    // preprocessing: pack weights, LN
    cvt_pack_kernel<<<(DM * NWIDE) / 256, 256>>>(Wk_sw, Wq, Wk, Wv, Wg, wpack_);
    cvt2_kernel<<<dim3(DM * DM / 256, 2), 256>>>(Wq_sw, Wo, w2_);
    ln_msa_kernel<<<NLROWS, 256>>>(msa, ln_msa_g, ln_msa_b, m_);

    // fused 5-way projection: [ksw | q | k | v | gate]
    wgemm_kernel<0><<<dim3(NLROWS / 128, NWIDE / 128), 256>>>(
        m_, wpack_, NLROWS, DM, NWIDE,
        ksw_, q_, k_, v_, gate_, bk_sw, bg, scale, nullptr);

    // qsw (rows of sequence 0): (m0 @ Wq_sw + bq_sw) * scale
    wgemm_kernel<1><<<dim3(LRES / 128, HD / 128), 256>>>(
        m_, WqSW, LRES, DM, HD,
        nullptr, nullptr, nullptr, nullptr, nullptr, bq_sw, nullptr, scale, qsw_);

    // seq weights + weighted q
    seqw_kernel<<<dim3(LRES, NH), 256>>>(qsw_, ksw_, sw_);
    qw_kernel<<<(NLROWS * HD / 4) / 256, 256>>>(q_, sw_, qw_);

    // logits
    logits_tc_kernel<<<dim3(LRES / 64, LRES / 64, NH), 256>>>(qw_, k_, logits_);

    // pair bias + softmax
    pairbias_kernel<<<(LRES * LRES) / 8, 256>>>(pair, ln_pair_g, ln_pair_b, Wb, bias_);
    rowsoftmax_kernel<<<dim3(LRES, NH), 128>>>(logits_, bias_, attn_);

    // attn @ v (gate fused)
    attnout_tc_kernel<<<dim3(LRES / 128, (NSEQ * DHD) / 64, NH), 256>>>(attn_, v_, gate_, aog_);

    // final: aog @ Wo + bo
    wgemm_kernel<1><<<dim3(NLROWS / 128, DM / 128), 256>>>(
        aog_, WO, NLROWS, DM, DM,
        nullptr, nullptr, nullptr, nullptr, nullptr, bo, nullptr, 1.f, out);
}